// round 14
// baseline (speedup 1.0000x reference)
#include <cuda_runtime.h>
#include <cuda_bf16.h>
#include <math.h>

// Problem constants
#define BSZ   32
#define TLEN  1024
#define DIN   768
#define HD    768
#define G3    2304          // 3*HD
#define FCN   512
#define NOUTC 39

typedef unsigned long long ull;
typedef unsigned short u16;

// ---------------------------------------------------------------------------
// Scratch (device globals; no allocation allowed)
// ---------------------------------------------------------------------------
__device__ float g_xproj[(size_t)BSZ * TLEN * G3];   // input projections [B,T,3H]
__device__ float g_fc   [(size_t)BSZ * TLEN * FCN];  // fc output

// bf16 hi/lo planes
__device__ u16 g_fh [(size_t)BSZ * TLEN * DIN];   // features hi
__device__ u16 g_fl [(size_t)BSZ * TLEN * DIN];   // features lo
__device__ u16 g_hhi[(size_t)BSZ * TLEN * HD];    // h hi (layer0 then layer1)
__device__ u16 g_hlo[(size_t)BSZ * TLEN * HD];    // h lo
__device__ u16 g_w0h[(size_t)G3 * DIN], g_w0l[(size_t)G3 * DIN];
__device__ u16 g_w1h[(size_t)G3 * HD],  g_w1l[(size_t)G3 * HD];
__device__ u16 g_fwh[(size_t)FCN * HD], g_fwl[(size_t)FCN * HD];

// Grid-barrier flags: monotonic, never reset; padded to 128B lines.
__device__ unsigned g_flags[96 * 32];

// ---------------------------------------------------------------------------
// Helpers
// ---------------------------------------------------------------------------
__device__ __forceinline__ void fma2(ull& d, ull a, ull b) {
    asm("fma.rn.f32x2 %0, %1, %2, %0;" : "+l"(d) : "l"(a), "l"(b));
}
__device__ __forceinline__ ull pack2(float lo, float hi) {
    ull d; asm("mov.b64 %0, {%1, %2};" : "=l"(d) : "f"(lo), "f"(hi)); return d;
}
__device__ __forceinline__ float2 unpack2(ull v) {
    float2 r; asm("mov.b64 {%0, %1}, %2;" : "=f"(r.x), "=f"(r.y) : "l"(v)); return r;
}
__device__ __forceinline__ unsigned bfpk(float hi_src, float lo_src) {
    unsigned r;
    asm("cvt.rn.bf16x2.f32 %0, %1, %2;" : "=r"(r) : "f"(hi_src), "f"(lo_src));
    return r;
}
__device__ __forceinline__ float bflo(unsigned p) { return __uint_as_float(p << 16); }
__device__ __forceinline__ float bfhi(unsigned p) { return __uint_as_float(p & 0xFFFF0000u); }

__device__ __forceinline__ void mma16816(float* d, const unsigned* a,
                                         const unsigned* b) {
    asm volatile(
        "mma.sync.aligned.m16n8k16.row.col.f32.bf16.bf16.f32 "
        "{%0,%1,%2,%3}, {%4,%5,%6,%7}, {%8,%9}, {%0,%1,%2,%3};"
        : "+f"(d[0]), "+f"(d[1]), "+f"(d[2]), "+f"(d[3])
        : "r"(a[0]), "r"(a[1]), "r"(a[2]), "r"(a[3]), "r"(b[0]), "r"(b[1]));
}
__device__ __forceinline__ void ldmx4(unsigned* r, unsigned saddr) {
    asm volatile("ldmatrix.sync.aligned.m8n8.x4.shared.b16 {%0,%1,%2,%3}, [%4];"
                 : "=r"(r[0]), "=r"(r[1]), "=r"(r[2]), "=r"(r[3]) : "r"(saddr));
}
__device__ __forceinline__ void ldmx2(unsigned* r, unsigned saddr) {
    asm volatile("ldmatrix.sync.aligned.m8n8.x2.shared.b16 {%0,%1}, [%2];"
                 : "=r"(r[0]), "=r"(r[1]) : "r"(saddr));
}
__device__ __forceinline__ void cp16(void* smem_dst, const void* gsrc) {
    unsigned s = (unsigned)__cvta_generic_to_shared(smem_dst);
    asm volatile("cp.async.cg.shared.global [%0], [%1], 16;" :: "r"(s), "l"(gsrc));
}
__device__ __forceinline__ void cp_commit() { asm volatile("cp.async.commit_group;"); }
template <int N>
__device__ __forceinline__ void cp_wait() {
    asm volatile("cp.async.wait_group %0;" :: "n"(N));
}

// ---------------------------------------------------------------------------
// Prep: fp32 -> bf16 hi/lo planes (elementwise, float4 granularity)
// ---------------------------------------------------------------------------
__global__ __launch_bounds__(256) void pack_hl(
    const float* __restrict__ src,
    u16* __restrict__ dhi, u16* __restrict__ dlo, int n4)
{
    const int i = blockIdx.x * 256 + threadIdx.x;
    if (i >= n4) return;
    float4 v = ((const float4*)src)[i];
    unsigned p0 = bfpk(v.x, v.x), p1 = bfpk(v.y, v.y);
    unsigned p2 = bfpk(v.z, v.z), p3 = bfpk(v.w, v.w);
    float r0 = v.x - bflo(p0), r1 = v.y - bflo(p1);
    float r2 = v.z - bflo(p2), r3 = v.w - bflo(p3);
    unsigned q0 = bfpk(r0, r0), q1 = bfpk(r1, r1);
    unsigned q2 = bfpk(r2, r2), q3 = bfpk(r3, r3);
    ushort4 hi, lo;
    hi.x = (u16)p0; hi.y = (u16)p1; hi.z = (u16)p2; hi.w = (u16)p3;
    lo.x = (u16)q0; lo.y = (u16)q1; lo.z = (u16)q2; lo.w = (u16)q3;
    ((ushort4*)dhi)[i] = hi;
    ((ushort4*)dlo)[i] = lo;
}

// ---------------------------------------------------------------------------
// Split-bf16 tensor GEMM: C[M,N] = act(A@W^T + bias), A/W as hi/lo planes.
// BM=128, BN=64, BK=64, 256 threads (8 warps: 4m x 2n), 3-pass split.
// ---------------------------------------------------------------------------
#define GP      144                           // smem row pitch (bytes)
#define SA_HI   0
#define SA_LO   (128 * GP)                    // 18432
#define SW_HI   (2 * 128 * GP)                // 36864
#define SW_LO   (SW_HI + 64 * GP)             // 46080
#define STAGE   (SW_LO + 64 * GP)             // 55296
#define GSMEM   (2 * STAGE)                   // 110592

template <int ACT>
__global__ __launch_bounds__(256) void gemm_bf16_hl(
    const u16* __restrict__ Ah, const u16* __restrict__ Al,
    const u16* __restrict__ Wh, const u16* __restrict__ Wl,
    const float* __restrict__ bias, float* __restrict__ C,
    int M, int N, int K)
{
    extern __shared__ char smg[];
    unsigned sbase;
    asm("{ .reg .u64 t; cvta.to.shared.u64 t, %1; cvt.u32.u64 %0, t; }"
        : "=r"(sbase) : "l"(smg));

    const int tid  = threadIdx.x;
    const int warp = tid >> 5;
    const int lane = tid & 31;
    const int wm   = warp >> 1;          // 0..3
    const int wn   = warp & 1;           // 0..1
    const int m0   = blockIdx.y * 128;
    const int n0   = blockIdx.x * 64;

    const int lr = tid >> 3;             // 0..31
    const int lc = tid & 7;              // 0..7 (16B chunk)

    const int NS = K / 64;

    auto load_slab = [&](int s) {
        const int k0 = s * 64;
        char* st = smg + (s & 1) * STAGE;
#pragma unroll
        for (int p = 0; p < 4; p++) {
            const int r = lr + p * 32;
            cp16(st + SA_HI + r * GP + lc * 16, Ah + (size_t)(m0 + r) * K + k0 + lc * 8);
            cp16(st + SA_LO + r * GP + lc * 16, Al + (size_t)(m0 + r) * K + k0 + lc * 8);
        }
#pragma unroll
        for (int p = 0; p < 2; p++) {
            const int r = lr + p * 32;
            cp16(st + SW_HI + r * GP + lc * 16, Wh + (size_t)(n0 + r) * K + k0 + lc * 8);
            cp16(st + SW_LO + r * GP + lc * 16, Wl + (size_t)(n0 + r) * K + k0 + lc * 8);
        }
        cp_commit();
    };

    float acc[2][4][4];
#pragma unroll
    for (int mt = 0; mt < 2; mt++)
#pragma unroll
        for (int nt = 0; nt < 4; nt++)
#pragma unroll
            for (int e = 0; e < 4; e++) acc[mt][nt][e] = 0.f;

    const int q  = lane >> 3;
    const int rq = (q & 1) * 8 + (lane & 7);
    const int qk = q >> 1;
    const int l2 = lane & 15;
    const int brow = l2 & 7;
    const int bk16 = ((l2 >> 3) & 1) * 16;

    load_slab(0);

    for (int s = 0; s < NS; s++) {
        if (s + 1 < NS) { load_slab(s + 1); cp_wait<1>(); }
        else           { cp_wait<0>(); }
        __syncthreads();

        const unsigned stA_hi = sbase + (s & 1) * STAGE + SA_HI;
        const unsigned stA_lo = sbase + (s & 1) * STAGE + SA_LO;
        const unsigned stW_hi = sbase + (s & 1) * STAGE + SW_HI;
        const unsigned stW_lo = sbase + (s & 1) * STAGE + SW_LO;

#pragma unroll
        for (int kt = 0; kt < 4; kt++) {
            unsigned ah[2][4], al[2][4], bh2[4][2], bl2[4][2];
#pragma unroll
            for (int mt = 0; mt < 2; mt++) {
                const int row = wm * 32 + mt * 16 + rq;
                ldmx4(ah[mt], stA_hi + row * GP + kt * 32 + qk * 16);
                ldmx4(al[mt], stA_lo + row * GP + kt * 32 + qk * 16);
            }
#pragma unroll
            for (int nt = 0; nt < 4; nt++) {
                const int row = wn * 32 + nt * 8 + brow;
                ldmx2(bh2[nt], stW_hi + row * GP + kt * 32 + bk16);
                ldmx2(bl2[nt], stW_lo + row * GP + kt * 32 + bk16);
            }
#pragma unroll
            for (int mt = 0; mt < 2; mt++)
#pragma unroll
                for (int nt = 0; nt < 4; nt++) {
                    mma16816(acc[mt][nt], ah[mt], bh2[nt]);
                    mma16816(acc[mt][nt], ah[mt], bl2[nt]);
                    mma16816(acc[mt][nt], al[mt], bh2[nt]);
                }
        }
        __syncthreads();
    }

    const float selu_scale = 1.0507009873554804934193349852946f;
    const float selu_alpha = 1.6732632423543772848170429916717f;
    const int r0 = lane >> 2;
    const int c0 = (lane & 3) * 2;
#pragma unroll
    for (int mt = 0; mt < 2; mt++)
#pragma unroll
        for (int nt = 0; nt < 4; nt++) {
            const int col = n0 + wn * 32 + nt * 8 + c0;
            const float b0 = bias[col], b1 = bias[col + 1];
#pragma unroll
            for (int h = 0; h < 2; h++) {
                const int row = m0 + wm * 32 + mt * 16 + r0 + h * 8;
                float v0 = acc[mt][nt][h * 2 + 0] + b0;
                float v1 = acc[mt][nt][h * 2 + 1] + b1;
                if (ACT == 1) {
                    v0 = selu_scale * (v0 > 0.f ? v0 : selu_alpha * (expf(v0) - 1.f));
                    v1 = selu_scale * (v1 > 0.f ? v1 : selu_alpha * (expf(v1) - 1.f));
                }
                *(float2*)(C + (size_t)row * N + col) = make_float2(v0, v1);
            }
        }
}

// ---------------------------------------------------------------------------
// FFMA2 GEMM (out_proj, N=39): C = tanh(A@W^T + b)
// ---------------------------------------------------------------------------
__global__ __launch_bounds__(256) void gemm_out_tanh(
    const float* __restrict__ A, const float* __restrict__ W,
    const float* __restrict__ bias, float* __restrict__ C,
    int M, int N, int K)
{
    __shared__ float As[8][128];
    __shared__ float Bs[8][128];

    const int tid  = threadIdx.x;
    const int m0   = blockIdx.y * 128;
    const int n0   = 0;
    const int lrow = tid >> 1;
    const int lk4  = (tid & 1) * 4;
    const int tx = tid & 15;
    const int ty = tid >> 4;

    ull acc2[8][4];
#pragma unroll
    for (int i = 0; i < 8; i++)
#pragma unroll
        for (int j = 0; j < 4; j++) acc2[i][j] = 0ull;

    const float* Arow = A + (size_t)(m0 + lrow) * K + lk4;
    const float* Wrow = W + (size_t)(n0 + lrow) * K + lk4;
    const bool   wok  = (n0 + lrow) < N;

    for (int k0 = 0; k0 < K; k0 += 8) {
        float4 av = *(const float4*)(Arow + k0);
        float4 wv = make_float4(0.f, 0.f, 0.f, 0.f);
        if (wok) wv = *(const float4*)(Wrow + k0);

        __syncthreads();
        As[lk4 + 0][lrow] = av.x; As[lk4 + 1][lrow] = av.y;
        As[lk4 + 2][lrow] = av.z; As[lk4 + 3][lrow] = av.w;
        Bs[lk4 + 0][lrow] = wv.x; Bs[lk4 + 1][lrow] = wv.y;
        Bs[lk4 + 2][lrow] = wv.z; Bs[lk4 + 3][lrow] = wv.w;
        __syncthreads();

#pragma unroll
        for (int kk = 0; kk < 8; kk++) {
            float a[8];
            *(float4*)(a)     = *(const float4*)&As[kk][ty * 4];
            *(float4*)(a + 4) = *(const float4*)&As[kk][64 + ty * 4];
            ulonglong2 b01 = *(const ulonglong2*)&Bs[kk][tx * 4];
            ulonglong2 b23 = *(const ulonglong2*)&Bs[kk][64 + tx * 4];
            ull bb[4] = { b01.x, b01.y, b23.x, b23.y };
            ull aa[8];
#pragma unroll
            for (int i = 0; i < 8; i++) aa[i] = pack2(a[i], a[i]);
#pragma unroll
            for (int i = 0; i < 8; i++)
#pragma unroll
                for (int j = 0; j < 4; j++)
                    fma2(acc2[i][j], aa[i], bb[j]);
        }
    }

#pragma unroll
    for (int i = 0; i < 8; i++) {
        const int m = m0 + ((i < 4) ? (ty * 4 + i) : (64 + ty * 4 + i - 4));
        float* crow = C + (size_t)m * N;
#pragma unroll
        for (int j = 0; j < 4; j++) {
            const int nf = n0 + ((j < 2) ? (tx * 4 + j * 2)
                                         : (64 + tx * 4 + (j - 2) * 2));
            float2 v = unpack2(acc2[i][j]);
            float vals[2] = { v.x, v.y };
#pragma unroll
            for (int s = 0; s < 2; s++) {
                const int n = nf + s;
                if (n < N) crow[n] = tanhf(vals[s] + bias[n]);
            }
        }
    }
}

// ---------------------------------------------------------------------------
// Persistent GRU layer (champion design) + two throttle-hardening deltas:
//   1. grid padded to 148 (blocks >= 96 exit immediately; leaves low-grid
//      issue-throttle regime per B300 docs)
//   2. __nanosleep backoff in the flag poll after the first miss (cuts
//      sustained acquire-spam into L2 while spinning)
// ---------------------------------------------------------------------------
#define NBLK    96
#define GRID_PAD 148
#define HPB     1552                         // bf16 row pitch (bytes)
#define OFF_HHI 0                            // 32 x 1552 = 49664
#define OFF_HLO 49664
#define OFF_WHI 99328                        // 24 x 1552 = 37248
#define OFF_WLO 136576
#define OFF_PRT 173824                       // 8*768 f32 = 24576
#define MMA_SMEM (OFF_PRT + 24576)           // 198400 B

__global__ __launch_bounds__(256) void gru_layer_wmma(
    const float* __restrict__ xproj,         // [B,T,3H] (gi, b_ih folded in)
    const float* __restrict__ w_hh,          // [3H, H] fp32
    const float* __restrict__ b_hh,          // [3H]
    u16* __restrict__ hhi,                   // [B,T,H] bf16-hi plane
    u16* __restrict__ hlo)                   // [B,T,H] bf16-lo plane
{
    if (blockIdx.x >= NBLK) return;          // grid padding blocks exit

    extern __shared__ char smc[];
    unsigned sbase;
    asm("{ .reg .u64 t; cvta.to.shared.u64 t, %1; cvt.u32.u64 %0, t; }"
        : "=r"(sbase) : "l"(smc));

    const int tid  = threadIdx.x;
    const int warp = tid >> 5;
    const int lane = tid & 31;
    const int u0   = blockIdx.x * 8;
    const unsigned flag_base = g_flags[blockIdx.x * 32];

    // ---- one-time: convert w slice (24x768 fp32) to bf16 hi/lo smem ----
    if (tid < 192) {
        const int n = tid % 24;
        const int c = tid / 24;
        const float* ws = w_hh + (size_t)((n >> 3) * HD + u0 + (n & 7)) * HD + c * 96;
#pragma unroll
        for (int j = 0; j < 12; j++) {
            float4 a = *(const float4*)(ws + j * 8);
            float4 b = *(const float4*)(ws + j * 8 + 4);
            unsigned h0 = bfpk(a.y, a.x), h1 = bfpk(a.w, a.z);
            unsigned h2 = bfpk(b.y, b.x), h3 = bfpk(b.w, b.z);
            unsigned l0 = bfpk(a.y - bfhi(h0), a.x - bflo(h0));
            unsigned l1 = bfpk(a.w - bfhi(h1), a.z - bflo(h1));
            unsigned l2 = bfpk(b.y - bfhi(h2), b.x - bflo(h2));
            unsigned l3 = bfpk(b.w - bfhi(h3), b.z - bflo(h3));
            const int off = n * HPB + (c * 96 + j * 8) * 2;
            *(uint4*)(smc + OFF_WHI + off) = make_uint4(h0, h1, h2, h3);
            *(uint4*)(smc + OFF_WLO + off) = make_uint4(l0, l1, l2, l3);
        }
    }
    __syncthreads();

    // ---- one-time: persistent B fragments for this warp's k-slice ----
    unsigned bh[3][6][2], bl[3][6][2];
    {
        const int l2 = lane & 15;
#pragma unroll
        for (int nt = 0; nt < 3; nt++)
#pragma unroll
            for (int kt = 0; kt < 6; kt++) {
                const int row = nt * 8 + (l2 & 7);
                const int kel = warp * 96 + kt * 16 + ((l2 >> 3) & 1) * 8;
                ldmx2(bh[nt][kt], sbase + OFF_WHI + row * HPB + kel * 2);
                ldmx2(bl[nt][kt], sbase + OFF_WLO + row * HPB + kel * 2);
            }
    }
    __syncthreads();

    // ---- gate decode ----
    const int bg = tid >> 3;
    const int ug = tid & 7;
    const float bias_r = b_hh[u0 + ug];
    const float bias_z = b_hh[HD + u0 + ug];
    const float bias_n = b_hh[2 * HD + u0 + ug];
    float hprev = 0.f;

    // ---- t = 0: gh = b_hh only ----
    {
        const size_t xb = ((size_t)bg * TLEN + 0) * G3 + (u0 + ug);
        const float gi_r = xproj[xb];
        const float gi_z = xproj[xb + HD];
        const float gi_n = xproj[xb + 2 * HD];
        const float r = 1.f / (1.f + expf(-(gi_r + bias_r)));
        const float z = 1.f / (1.f + expf(-(gi_z + bias_z)));
        const float n = tanhf(gi_n + r * bias_n);
        hprev = (1.f - z) * n;
        const size_t hidx = ((size_t)bg * TLEN + 0) * HD + (u0 + ug);
        unsigned p = bfpk(hprev, hprev);
        float res = hprev - bflo(p);
        unsigned ql = bfpk(res, res);
        hhi[hidx] = (u16)p;
        hlo[hidx] = (u16)ql;
        __syncthreads();
        if (tid == 0)
            asm volatile("st.release.gpu.global.u32 [%0], %1;"
                         :: "l"(&g_flags[blockIdx.x * 32]), "r"(flag_base + 1u) : "memory");
    }

    float* prt = (float*)(smc + OFF_PRT);
    const int src0 = 12 * warp;               // first source block for this warp

    for (int t = 1; t < TLEN; t++) {
        // --- warp-granular wait with nanosleep backoff after first miss ---
        const unsigned need = flag_base + (unsigned)t;
        if (lane < 12) {
            const unsigned* fp = &g_flags[(src0 + lane) * 32];
            unsigned v;
            asm volatile("ld.acquire.gpu.global.u32 %0, [%1];"
                         : "=r"(v) : "l"(fp) : "memory");
            while ((int)(v - need) < 0) {
                __nanosleep(64);
                asm volatile("ld.acquire.gpu.global.u32 %0, [%1];"
                             : "=r"(v) : "l"(fp) : "memory");
            }
        }
        __syncwarp();

        // gate-input prefetch (independent; hidden under copy + mma)
        const size_t xb = ((size_t)bg * TLEN + t) * G3 + (u0 + ug);
        const float gi_r = xproj[xb];
        const float gi_z = xproj[xb + HD];
        const float gi_n = xproj[xb + 2 * HD];

        // --- stage h_{t-1} slice: straight plane copy, no conversion ---
        {
            const size_t rb = ((size_t)lane * TLEN + (t - 1)) * HD + warp * 96;
            const u16* sh = hhi + rb;
            const u16* sl = hlo + rb;
            char* dh = smc + OFF_HHI + lane * HPB + (warp * 96) * 2;
            char* dl = smc + OFF_HLO + lane * HPB + (warp * 96) * 2;
#pragma unroll
            for (int j = 0; j < 12; j++) {
                uint4 vh = __ldcg((const uint4*)(sh + j * 8));
                uint4 vl = __ldcg((const uint4*)(sl + j * 8));
                *(uint4*)(dh + j * 16) = vh;
                *(uint4*)(dl + j * 16) = vl;
            }
        }
        __syncwarp();

        // --- mma: 6 k-tiles, 2 m x 3 n, 3 split passes ---
        float acc[2][3][4];
#pragma unroll
        for (int mt = 0; mt < 2; mt++)
#pragma unroll
            for (int nt = 0; nt < 3; nt++)
#pragma unroll
                for (int e = 0; e < 4; e++) acc[mt][nt][e] = 0.f;

        const int q = lane >> 3;
        const int rq = (q & 1) * 8 + (lane & 7);
#pragma unroll
        for (int kt = 0; kt < 6; kt++) {
            const int kel = warp * 96 + kt * 16 + (q >> 1) * 8;
            unsigned ah[2][4], al[2][4];
#pragma unroll
            for (int mt = 0; mt < 2; mt++) {
                const int row = mt * 16 + rq;
                ldmx4(ah[mt], sbase + OFF_HHI + row * HPB + kel * 2);
                ldmx4(al[mt], sbase + OFF_HLO + row * HPB + kel * 2);
            }
#pragma unroll
            for (int mt = 0; mt < 2; mt++)
#pragma unroll
                for (int nt = 0; nt < 3; nt++) {
                    mma16816(acc[mt][nt], ah[mt], bh[nt][kt]);
                    mma16816(acc[mt][nt], ah[mt], bl[nt][kt]);
                    mma16816(acc[mt][nt], al[mt], bh[nt][kt]);
                }
        }

        // --- dump partials ---
        {
            float* wp = prt + warp * 768;
            const int r0 = lane >> 2;
            const int c0 = (lane & 3) * 2;
#pragma unroll
            for (int mt = 0; mt < 2; mt++)
#pragma unroll
                for (int nt = 0; nt < 3; nt++) {
                    const int base = (mt * 16 + r0) * 24 + nt * 8 + c0;
                    *(float2*)(wp + base)          = make_float2(acc[mt][nt][0], acc[mt][nt][1]);
                    *(float2*)(wp + base + 8 * 24) = make_float2(acc[mt][nt][2], acc[mt][nt][3]);
                }
        }
        __syncthreads();

        // --- gates ---
        {
            float gh[3];
#pragma unroll
            for (int g = 0; g < 3; g++) {
                const int o = bg * 24 + g * 8 + ug;
                float s = 0.f;
#pragma unroll
                for (int w = 0; w < 8; w++) s += prt[w * 768 + o];
                gh[g] = s;
            }
            const float r = 1.f / (1.f + expf(-(gi_r + gh[0] + bias_r)));
            const float z = 1.f / (1.f + expf(-(gi_z + gh[1] + bias_z)));
            const float n = tanhf(gi_n + r * (gh[2] + bias_n));
            const float hnew = (1.f - z) * n + z * hprev;
            hprev = hnew;
            const size_t hidx = ((size_t)bg * TLEN + t) * HD + (u0 + ug);
            unsigned p = bfpk(hnew, hnew);
            float res = hnew - bflo(p);
            unsigned ql = bfpk(res, res);
            hhi[hidx] = (u16)p;
            hlo[hidx] = (u16)ql;
        }
        __syncthreads();   // all h stores issued; prt consumable next step

        if (tid == 0)
            asm volatile("st.release.gpu.global.u32 [%0], %1;"
                         :: "l"(&g_flags[blockIdx.x * 32]),
                            "r"(flag_base + (unsigned)(t + 1)) : "memory");
    }
}

// ---------------------------------------------------------------------------
// Launch: 10 graph nodes.
// ---------------------------------------------------------------------------
extern "C" void kernel_launch(void* const* d_in, const int* in_sizes, int n_in,
                              void* d_out, int out_size)
{
    const float* features = (const float*)d_in[0];
    const float* w_ih0 = (const float*)d_in[2];
    const float* w_hh0 = (const float*)d_in[3];
    const float* b_ih0 = (const float*)d_in[4];
    const float* b_hh0 = (const float*)d_in[5];
    const float* w_ih1 = (const float*)d_in[6];
    const float* w_hh1 = (const float*)d_in[7];
    const float* b_ih1 = (const float*)d_in[8];
    const float* b_hh1 = (const float*)d_in[9];
    const float* fc_w  = (const float*)d_in[10];
    const float* fc_b  = (const float*)d_in[11];
    const float* out_w = (const float*)d_in[12];
    const float* out_b = (const float*)d_in[13];

    float *xproj, *fcb;
    u16 *fh, *fl, *hhi, *hlo, *w0h, *w0l, *w1h, *w1l, *fwh, *fwl;
    cudaGetSymbolAddress((void**)&xproj, g_xproj);
    cudaGetSymbolAddress((void**)&fcb,   g_fc);
    cudaGetSymbolAddress((void**)&fh,  g_fh);
    cudaGetSymbolAddress((void**)&fl,  g_fl);
    cudaGetSymbolAddress((void**)&hhi, g_hhi);
    cudaGetSymbolAddress((void**)&hlo, g_hlo);
    cudaGetSymbolAddress((void**)&w0h, g_w0h);
    cudaGetSymbolAddress((void**)&w0l, g_w0l);
    cudaGetSymbolAddress((void**)&w1h, g_w1h);
    cudaGetSymbolAddress((void**)&w1l, g_w1l);
    cudaGetSymbolAddress((void**)&fwh, g_fwh);
    cudaGetSymbolAddress((void**)&fwl, g_fwl);

    static bool attr_set = false;
    if (!attr_set) {
        cudaFuncSetAttribute(gru_layer_wmma,
                             cudaFuncAttributeMaxDynamicSharedMemorySize, (int)MMA_SMEM);
        cudaFuncSetAttribute(gemm_bf16_hl<0>,
                             cudaFuncAttributeMaxDynamicSharedMemorySize, (int)GSMEM);
        cudaFuncSetAttribute(gemm_bf16_hl<1>,
                             cudaFuncAttributeMaxDynamicSharedMemorySize, (int)GSMEM);
        attr_set = true;
    }

    const int M = BSZ * TLEN;                 // 32768

    // Prep: pack fp32 -> bf16 hi/lo planes
    {
        int n4 = (BSZ * TLEN * DIN) / 4;      // features
        pack_hl<<<(n4 + 255) / 256, 256>>>(features, fh, fl, n4);
        n4 = (G3 * DIN) / 4;
        pack_hl<<<(n4 + 255) / 256, 256>>>(w_ih0, w0h, w0l, n4);
        n4 = (G3 * HD) / 4;
        pack_hl<<<(n4 + 255) / 256, 256>>>(w_ih1, w1h, w1l, n4);
        n4 = (FCN * HD) / 4;
        pack_hl<<<(n4 + 255) / 256, 256>>>(fc_w, fwh, fwl, n4);
    }

    // Layer 0: input projection (bias b_ih folded in)
    gemm_bf16_hl<0><<<dim3(G3 / 64, M / 128), 256, GSMEM>>>(
        fh, fl, w0h, w0l, b_ih0, xproj, M, G3, DIN);
    gru_layer_wmma<<<GRID_PAD, 256, MMA_SMEM>>>(xproj, w_hh0, b_hh0, hhi, hlo);

    // Layer 1: input projection reads layer-0 h planes
    gemm_bf16_hl<0><<<dim3(G3 / 64, M / 128), 256, GSMEM>>>(
        hhi, hlo, w1h, w1l, b_ih1, xproj, M, G3, HD);
    gru_layer_wmma<<<GRID_PAD, 256, MMA_SMEM>>>(xproj, w_hh1, b_hh1, hhi, hlo);

    // fc + SELU (reads layer-1 h planes)
    gemm_bf16_hl<1><<<dim3(FCN / 64, M / 128), 256, GSMEM>>>(
        hhi, hlo, fwh, fwl, fc_b, fcb, M, FCN, HD);

    // out_proj + tanh (fp32 FFMA2; N=39)
    gemm_out_tanh<<<dim3(1, M / 128), 256>>>(fcb, out_w, out_b, (float*)d_out,
                                             M, NOUTC, FCN);
}

// round 15
// speedup vs baseline: 2.3933x; 2.3933x over previous
#include <cuda_runtime.h>
#include <cuda_bf16.h>
#include <math.h>

// Problem constants
#define BSZ   32
#define TLEN  1024
#define DIN   768
#define HD    768
#define G3    2304
#define FCN   512
#define NOUTC 39

typedef unsigned long long ull;
typedef unsigned short u16;

// ---------------------------------------------------------------------------
// Scratch (device globals)
// ---------------------------------------------------------------------------
__device__ float g_xproj [(size_t)BSZ * TLEN * G3];   // layer-0 input projections
__device__ float g_xproj2[(size_t)BSZ * TLEN * G3];   // layer-1 input projections
__device__ float g_fc    [(size_t)BSZ * TLEN * FCN];  // fc output
__device__ float g_cb0[G3], g_cb1[G3];                // combined biases (b_ih + b_hh[r,z])

// bf16 hi/lo planes
__device__ u16 g_fh [(size_t)BSZ * TLEN * DIN], g_fl [(size_t)BSZ * TLEN * DIN];
__device__ u16 g_hhi[(size_t)BSZ * TLEN * HD],  g_hlo[(size_t)BSZ * TLEN * HD];
__device__ u16 g_w0h[(size_t)G3 * DIN], g_w0l[(size_t)G3 * DIN];
__device__ u16 g_w1h[(size_t)G3 * HD],  g_w1l[(size_t)G3 * HD];
__device__ u16 g_fwh[(size_t)FCN * HD], g_fwl[(size_t)FCN * HD];

// Flags: monotonic, +2048/replay (h), +16/replay (consumers); 128B lines.
__device__ unsigned g_flags [96 * 32];
__device__ unsigned g_cflags[48 * 32];

// ---------------------------------------------------------------------------
// Helpers
// ---------------------------------------------------------------------------
__device__ __forceinline__ void fma2(ull& d, ull a, ull b) {
    asm("fma.rn.f32x2 %0, %1, %2, %0;" : "+l"(d) : "l"(a), "l"(b));
}
__device__ __forceinline__ ull pack2(float lo, float hi) {
    ull d; asm("mov.b64 %0, {%1, %2};" : "=l"(d) : "f"(lo), "f"(hi)); return d;
}
__device__ __forceinline__ float2 unpack2(ull v) {
    float2 r; asm("mov.b64 {%0, %1}, %2;" : "=f"(r.x), "=f"(r.y) : "l"(v)); return r;
}
__device__ __forceinline__ unsigned bfpk(float hi_src, float lo_src) {
    unsigned r;
    asm("cvt.rn.bf16x2.f32 %0, %1, %2;" : "=r"(r) : "f"(hi_src), "f"(lo_src));
    return r;
}
__device__ __forceinline__ float bflo(unsigned p) { return __uint_as_float(p << 16); }
__device__ __forceinline__ float bfhi(unsigned p) { return __uint_as_float(p & 0xFFFF0000u); }

__device__ __forceinline__ void mma16816(float* d, const unsigned* a, const unsigned* b) {
    asm volatile(
        "mma.sync.aligned.m16n8k16.row.col.f32.bf16.bf16.f32 "
        "{%0,%1,%2,%3}, {%4,%5,%6,%7}, {%8,%9}, {%0,%1,%2,%3};"
        : "+f"(d[0]), "+f"(d[1]), "+f"(d[2]), "+f"(d[3])
        : "r"(a[0]), "r"(a[1]), "r"(a[2]), "r"(a[3]), "r"(b[0]), "r"(b[1]));
}
__device__ __forceinline__ void ldmx4(unsigned* r, unsigned saddr) {
    asm volatile("ldmatrix.sync.aligned.m8n8.x4.shared.b16 {%0,%1,%2,%3}, [%4];"
                 : "=r"(r[0]), "=r"(r[1]), "=r"(r[2]), "=r"(r[3]) : "r"(saddr));
}
__device__ __forceinline__ void ldmx2(unsigned* r, unsigned saddr) {
    asm volatile("ldmatrix.sync.aligned.m8n8.x2.shared.b16 {%0,%1}, [%2];"
                 : "=r"(r[0]), "=r"(r[1]) : "r"(saddr));
}
__device__ __forceinline__ void cp16(void* smem_dst, const void* gsrc) {
    unsigned s = (unsigned)__cvta_generic_to_shared(smem_dst);
    asm volatile("cp.async.cg.shared.global [%0], [%1], 16;" :: "r"(s), "l"(gsrc));
}
__device__ __forceinline__ void cp_commit() { asm volatile("cp.async.commit_group;"); }
template <int N>
__device__ __forceinline__ void cp_wait() {
    asm volatile("cp.async.wait_group %0;" :: "n"(N));
}
__device__ __forceinline__ unsigned ld_acq(const unsigned* p) {
    unsigned v;
    asm volatile("ld.acquire.gpu.global.u32 %0, [%1];" : "=r"(v) : "l"(p) : "memory");
    return v;
}
__device__ __forceinline__ void st_rel(unsigned* p, unsigned v) {
    asm volatile("st.release.gpu.global.u32 [%0], %1;" :: "l"(p), "r"(v) : "memory");
}

// ---------------------------------------------------------------------------
// Prep kernels
// ---------------------------------------------------------------------------
__global__ __launch_bounds__(256) void pack_hl(
    const float* __restrict__ src, u16* __restrict__ dhi, u16* __restrict__ dlo, int n4)
{
    const int i = blockIdx.x * 256 + threadIdx.x;
    if (i >= n4) return;
    float4 v = ((const float4*)src)[i];
    unsigned p0 = bfpk(v.x, v.x), p1 = bfpk(v.y, v.y);
    unsigned p2 = bfpk(v.z, v.z), p3 = bfpk(v.w, v.w);
    float r0 = v.x - bflo(p0), r1 = v.y - bflo(p1);
    float r2 = v.z - bflo(p2), r3 = v.w - bflo(p3);
    unsigned q0 = bfpk(r0, r0), q1 = bfpk(r1, r1);
    unsigned q2 = bfpk(r2, r2), q3 = bfpk(r3, r3);
    ushort4 hi, lo;
    hi.x = (u16)p0; hi.y = (u16)p1; hi.z = (u16)p2; hi.w = (u16)p3;
    lo.x = (u16)q0; lo.y = (u16)q1; lo.z = (u16)q2; lo.w = (u16)q3;
    ((ushort4*)dhi)[i] = hi;
    ((ushort4*)dlo)[i] = lo;
}

__global__ __launch_bounds__(256) void combine_bias(
    const float* __restrict__ bih, const float* __restrict__ bhh, float* __restrict__ out)
{
    const int i = blockIdx.x * 256 + threadIdx.x;
    if (i < G3) out[i] = bih[i] + (i < 2 * HD ? bhh[i] : 0.f);
}

// ---------------------------------------------------------------------------
// Split-bf16 GEMM tile (device fn). BM=128, BN=64, BK=64, K=768 fixed.
// Works inside 256- or 512-thread blocks (compute gated to tid<256).
// ---------------------------------------------------------------------------
#define GP      144
#define SA_HI   0
#define SA_LO   (128 * GP)
#define SW_HI   (2 * 128 * GP)
#define SW_LO   (SW_HI + 64 * GP)
#define STAGE   (SW_LO + 64 * GP)            // 55296
#define GSMEM   (2 * STAGE)                  // 110592

__device__ __forceinline__ void gemm_tile_hl(
    char* smg, unsigned sbase,
    const u16* __restrict__ Ah, const u16* __restrict__ Al,
    const u16* __restrict__ Wh, const u16* __restrict__ Wl,
    const float* __restrict__ bias, float* __restrict__ C,
    int m0, int n0, int N, int ACT)
{
    const int tid  = threadIdx.x;
    const int warp = tid >> 5;
    const int lane = tid & 31;
    const int wm   = warp >> 1;
    const int wn   = warp & 1;
    const int lr   = (tid >> 3) & 31;
    const int lc   = tid & 7;
    const bool act25 = (tid < 256);
    const int K = 768, NS = 12;

    float acc[2][4][4];
#pragma unroll
    for (int mt = 0; mt < 2; mt++)
#pragma unroll
        for (int nt = 0; nt < 4; nt++)
#pragma unroll
            for (int e = 0; e < 4; e++) acc[mt][nt][e] = 0.f;

    const int q  = lane >> 3;
    const int rq = (q & 1) * 8 + (lane & 7);
    const int qk = q >> 1;
    const int l2 = lane & 15;
    const int brow = l2 & 7;
    const int bk16 = ((l2 >> 3) & 1) * 16;

    // slab 0
    if (act25) {
        char* st = smg;
#pragma unroll
        for (int p = 0; p < 4; p++) {
            const int r = lr + p * 32;
            cp16(st + SA_HI + r * GP + lc * 16, Ah + (size_t)(m0 + r) * K + lc * 8);
            cp16(st + SA_LO + r * GP + lc * 16, Al + (size_t)(m0 + r) * K + lc * 8);
        }
#pragma unroll
        for (int p = 0; p < 2; p++) {
            const int r = lr + p * 32;
            cp16(st + SW_HI + r * GP + lc * 16, Wh + (size_t)(n0 + r) * K + lc * 8);
            cp16(st + SW_LO + r * GP + lc * 16, Wl + (size_t)(n0 + r) * K + lc * 8);
        }
        cp_commit();
    }

    for (int s = 0; s < NS; s++) {
        if (s + 1 < NS) {
            if (act25) {
                const int k0 = (s + 1) * 64;
                char* st = smg + ((s + 1) & 1) * STAGE;
#pragma unroll
                for (int p = 0; p < 4; p++) {
                    const int r = lr + p * 32;
                    cp16(st + SA_HI + r * GP + lc * 16, Ah + (size_t)(m0 + r) * K + k0 + lc * 8);
                    cp16(st + SA_LO + r * GP + lc * 16, Al + (size_t)(m0 + r) * K + k0 + lc * 8);
                }
#pragma unroll
                for (int p = 0; p < 2; p++) {
                    const int r = lr + p * 32;
                    cp16(st + SW_HI + r * GP + lc * 16, Wh + (size_t)(n0 + r) * K + k0 + lc * 8);
                    cp16(st + SW_LO + r * GP + lc * 16, Wl + (size_t)(n0 + r) * K + k0 + lc * 8);
                }
                cp_commit();
            }
            cp_wait<1>();
        } else {
            cp_wait<0>();
        }
        __syncthreads();

        if (warp < 8) {
            const unsigned stA_hi = sbase + (s & 1) * STAGE + SA_HI;
            const unsigned stA_lo = sbase + (s & 1) * STAGE + SA_LO;
            const unsigned stW_hi = sbase + (s & 1) * STAGE + SW_HI;
            const unsigned stW_lo = sbase + (s & 1) * STAGE + SW_LO;
#pragma unroll
            for (int kt = 0; kt < 4; kt++) {
                unsigned ah[2][4], al[2][4], bh2[4][2], bl2[4][2];
#pragma unroll
                for (int mt = 0; mt < 2; mt++) {
                    const int row = wm * 32 + mt * 16 + rq;
                    ldmx4(ah[mt], stA_hi + row * GP + kt * 32 + qk * 16);
                    ldmx4(al[mt], stA_lo + row * GP + kt * 32 + qk * 16);
                }
#pragma unroll
                for (int nt = 0; nt < 4; nt++) {
                    const int row = wn * 32 + nt * 8 + brow;
                    ldmx2(bh2[nt], stW_hi + row * GP + kt * 32 + bk16);
                    ldmx2(bl2[nt], stW_lo + row * GP + kt * 32 + bk16);
                }
#pragma unroll
                for (int mt = 0; mt < 2; mt++)
#pragma unroll
                    for (int nt = 0; nt < 4; nt++) {
                        mma16816(acc[mt][nt], ah[mt], bh2[nt]);
                        mma16816(acc[mt][nt], ah[mt], bl2[nt]);
                        mma16816(acc[mt][nt], al[mt], bh2[nt]);
                    }
            }
        }
        __syncthreads();
    }

    if (warp < 8) {
        const float selu_scale = 1.0507009873554804934193349852946f;
        const float selu_alpha = 1.6732632423543772848170429916717f;
        const int r0 = lane >> 2;
        const int c0 = (lane & 3) * 2;
#pragma unroll
        for (int mt = 0; mt < 2; mt++)
#pragma unroll
            for (int nt = 0; nt < 4; nt++) {
                const int col = n0 + wn * 32 + nt * 8 + c0;
                const float b0 = bias[col], b1 = bias[col + 1];
#pragma unroll
                for (int h = 0; h < 2; h++) {
                    const int row = m0 + wm * 32 + mt * 16 + r0 + h * 8;
                    float v0 = acc[mt][nt][h * 2 + 0] + b0;
                    float v1 = acc[mt][nt][h * 2 + 1] + b1;
                    if (ACT == 1) {
                        v0 = selu_scale * (v0 > 0.f ? v0 : selu_alpha * (expf(v0) - 1.f));
                        v1 = selu_scale * (v1 > 0.f ? v1 : selu_alpha * (expf(v1) - 1.f));
                    }
                    *(float2*)(C + (size_t)row * N + col) = make_float2(v0, v1);
                }
            }
    }
}

// Standalone GEMM (xproj0)
__global__ __launch_bounds__(256) void gemm_std(
    const u16* __restrict__ Ah, const u16* __restrict__ Al,
    const u16* __restrict__ Wh, const u16* __restrict__ Wl,
    const float* __restrict__ bias, float* __restrict__ C, int N)
{
    extern __shared__ char smg[];
    unsigned sbase;
    asm("{ .reg .u64 t; cvta.to.shared.u64 t, %1; cvt.u32.u64 %0, t; }"
        : "=r"(sbase) : "l"(smg));
    gemm_tile_hl(smg, sbase, Ah, Al, Wh, Wl, bias, C,
                 blockIdx.y * 128, blockIdx.x * 64, N, 0);
}

// ---------------------------------------------------------------------------
// out_proj (fp32 FFMA2, N=39)
// ---------------------------------------------------------------------------
__global__ __launch_bounds__(256) void gemm_out_tanh(
    const float* __restrict__ A, const float* __restrict__ W,
    const float* __restrict__ bias, float* __restrict__ C,
    int M, int N, int K)
{
    __shared__ float As[8][128];
    __shared__ float Bs[8][128];

    const int tid  = threadIdx.x;
    const int m0   = blockIdx.y * 128;
    const int lrow = tid >> 1;
    const int lk4  = (tid & 1) * 4;
    const int tx = tid & 15;
    const int ty = tid >> 4;

    ull acc2[8][4];
#pragma unroll
    for (int i = 0; i < 8; i++)
#pragma unroll
        for (int j = 0; j < 4; j++) acc2[i][j] = 0ull;

    const float* Arow = A + (size_t)(m0 + lrow) * K + lk4;
    const float* Wrow = W + (size_t)lrow * K + lk4;
    const bool   wok  = lrow < N;

    for (int k0 = 0; k0 < K; k0 += 8) {
        float4 av = *(const float4*)(Arow + k0);
        float4 wv = make_float4(0.f, 0.f, 0.f, 0.f);
        if (wok) wv = *(const float4*)(Wrow + k0);

        __syncthreads();
        As[lk4 + 0][lrow] = av.x; As[lk4 + 1][lrow] = av.y;
        As[lk4 + 2][lrow] = av.z; As[lk4 + 3][lrow] = av.w;
        Bs[lk4 + 0][lrow] = wv.x; Bs[lk4 + 1][lrow] = wv.y;
        Bs[lk4 + 2][lrow] = wv.z; Bs[lk4 + 3][lrow] = wv.w;
        __syncthreads();

#pragma unroll
        for (int kk = 0; kk < 8; kk++) {
            float a[8];
            *(float4*)(a)     = *(const float4*)&As[kk][ty * 4];
            *(float4*)(a + 4) = *(const float4*)&As[kk][64 + ty * 4];
            ulonglong2 b01 = *(const ulonglong2*)&Bs[kk][tx * 4];
            ulonglong2 b23 = *(const ulonglong2*)&Bs[kk][64 + tx * 4];
            ull bb[4] = { b01.x, b01.y, b23.x, b23.y };
            ull aa[8];
#pragma unroll
            for (int i = 0; i < 8; i++) aa[i] = pack2(a[i], a[i]);
#pragma unroll
            for (int i = 0; i < 8; i++)
#pragma unroll
                for (int j = 0; j < 4; j++)
                    fma2(acc2[i][j], aa[i], bb[j]);
        }
    }

#pragma unroll
    for (int i = 0; i < 8; i++) {
        const int m = m0 + ((i < 4) ? (ty * 4 + i) : (64 + ty * 4 + i - 4));
        float* crow = C + (size_t)m * N;
#pragma unroll
        for (int j = 0; j < 4; j++) {
            const int nf = (j < 2) ? (tx * 4 + j * 2) : (64 + tx * 4 + (j - 2) * 2);
            float2 v = unpack2(acc2[i][j]);
            float vals[2] = { v.x, v.y };
#pragma unroll
            for (int s = 0; s < 2; s++) {
                const int n = nf + s;
                if (n < N) crow[n] = tanhf(vals[s] + bias[n]);
            }
        }
    }
}

// ---------------------------------------------------------------------------
// Fused persistent kernel: blocks 0-95 = GRU recurrence (2 batch groups x 48),
// blocks 96-143 = trailing FF-GEMM consumers.
// Recurrence block: 512 threads, 16 units, warp=(k-slice 0..7, n-half 0..1),
// B-frags register-resident, m16 A tile = the group's 16 batches.
// ---------------------------------------------------------------------------
#define HPB      1552
#define OFF_AH   0
#define OFF_AL   24832                       // 16*1552
#define OFF_PRT  49664                       // floats from here: 8*772
#define SCR_HI   0                           // init-only W scratch (24*1552)
#define SCR_LO   37248
#define FUS_SMEM GSMEM                       // 110592 (covers both roles)

__global__ __launch_bounds__(512, 1) void fused_layer(
    const float* __restrict__ xp,            // [B,T,3H] (combined bias folded for r,z)
    const float* __restrict__ w_hh,          // [3H,H] fp32
    const float* __restrict__ b_hh,          // [3H] (n-gate bias used)
    u16* __restrict__ hhi, u16* __restrict__ hlo,
    const u16* __restrict__ cAh, const u16* __restrict__ cAl,
    const u16* __restrict__ cWh, const u16* __restrict__ cWl,
    const float* __restrict__ cbias, float* __restrict__ cC,
    int cN, int cACT, unsigned base_off)
{
    extern __shared__ char smc[];
    unsigned sbase;
    asm("{ .reg .u64 t; cvta.to.shared.u64 t, %1; cvt.u32.u64 %0, t; }"
        : "=r"(sbase) : "l"(smc));
    const int tid = threadIdx.x;

    // ======================= CONSUMER BLOCKS =======================
    if (blockIdx.x >= 96) {
        const int cid = blockIdx.x - 96;
        const unsigned f = ld_acq(&g_flags[0]);
        const unsigned base = (f / 2048u) * 2048u + base_off;
        const int tnt = cN / 64;

        for (int tc = 0; tc < 8; tc++) {
            const unsigned target = base + (unsigned)((tc + 1) * 128);
            if (tid < 96) {
                while ((int)(ld_acq(&g_flags[tid * 32]) - target) < 0) { }
            }
            __syncthreads();
            for (int i = cid; i < 32 * tnt; i += 48) {
                const int b  = i / tnt;
                const int nt = i % tnt;
                gemm_tile_hl(smc, sbase, cAh, cAl, cWh, cWl, cbias, cC,
                             b * TLEN + tc * 128, nt * 64, cN, cACT);
            }
        }
        return;
    }

    // ======================= RECURRENCE BLOCKS =======================
    const int grp  = blockIdx.x / 48;        // batch group (16 batches)
    const int ub   = blockIdx.x % 48;
    const int u0g  = ub * 16;                // unit base
    const int bG0  = grp * 16;               // batch base
    const int warp = tid >> 5;
    const int lane = tid & 31;
    const int ks   = warp >> 1;              // k-slice 0..7 (96 wide)
    const int nh   = warp & 1;               // n-half 0..1 (24 rows)
    const unsigned flag_base = g_flags[blockIdx.x * 32];

    // ---- W init: 2 passes through scratch; frags -> registers ----
    unsigned bh[3][6][2], bl[3][6][2];
    for (int p = 0; p < 2; p++) {
        for (int i = tid; i < 24 * 96; i += 512) {
            const int r  = i / 96;            // scratch row 0..23
            const int kc = (i % 96) * 8;
            const int rg = p * 24 + r;        // gh row 0..47 (gate*16+unit)
            const int gate = rg >> 4, ul = rg & 15;
            const float* ws = w_hh + (size_t)(gate * HD + u0g + ul) * HD + kc;
            float4 a = *(const float4*)(ws);
            float4 b = *(const float4*)(ws + 4);
            unsigned h0 = bfpk(a.y, a.x), h1 = bfpk(a.w, a.z);
            unsigned h2 = bfpk(b.y, b.x), h3 = bfpk(b.w, b.z);
            unsigned l0 = bfpk(a.y - bfhi(h0), a.x - bflo(h0));
            unsigned l1 = bfpk(a.w - bfhi(h1), a.z - bflo(h1));
            unsigned l2_ = bfpk(b.y - bfhi(h2), b.x - bflo(h2));
            unsigned l3 = bfpk(b.w - bfhi(h3), b.z - bflo(h3));
            *(uint4*)(smc + SCR_HI + r * HPB + kc * 2) = make_uint4(h0, h1, h2, h3);
            *(uint4*)(smc + SCR_LO + r * HPB + kc * 2) = make_uint4(l0, l1, l2_, l3);
        }
        __syncthreads();
        if (nh == p) {
            const int l2 = lane & 15;
#pragma unroll
            for (int nt = 0; nt < 3; nt++)
#pragma unroll
                for (int kt = 0; kt < 6; kt++) {
                    const int row = nt * 8 + (l2 & 7);
                    const int kel = ks * 96 + kt * 16 + ((l2 >> 3) & 1) * 8;
                    ldmx2(bh[nt][kt], sbase + SCR_HI + row * HPB + kel * 2);
                    ldmx2(bl[nt][kt], sbase + SCR_LO + row * HPB + kel * 2);
                }
        }
        __syncthreads();
    }

    // ---- gate decode (tid < 256) ----
    const int bg = tid >> 4;                 // local batch 0..15
    const int ug = tid & 15;                 // local unit 0..15
    float bias_n = 0.f, hprev = 0.f;
    if (tid < 256) bias_n = b_hh[2 * HD + u0g + ug];

    // ---- t = 0: gh = 0 (biases folded into xp for r,z) ----
    if (tid < 256) {
        const size_t xb = ((size_t)(bG0 + bg) * TLEN + 0) * G3 + (u0g + ug);
        const float gi_r = xp[xb];
        const float gi_z = xp[xb + HD];
        const float gi_n = xp[xb + 2 * HD];
        const float r = 1.f / (1.f + expf(-gi_r));
        const float z = 1.f / (1.f + expf(-gi_z));
        const float n = tanhf(gi_n + r * bias_n);
        hprev = (1.f - z) * n;
        const size_t hidx = ((size_t)(bG0 + bg) * TLEN + 0) * HD + (u0g + ug);
        unsigned ph = bfpk(hprev, hprev);
        float res = hprev - bflo(ph);
        unsigned pl = bfpk(res, res);
        hhi[hidx] = (u16)ph;
        hlo[hidx] = (u16)pl;
    }
    __syncthreads();
    if (tid == 0) st_rel(&g_flags[blockIdx.x * 32], flag_base + 1u);

    float* prt = (float*)(smc + OFF_PRT);

    for (int t = 1; t < TLEN; t++) {
        // --- poll: 6 source blocks for this warp's k-slice ---
        const unsigned need = flag_base + (unsigned)t;
        if (lane < 6) {
            const unsigned* fp = &g_flags[(grp * 48 + ks * 6 + lane) * 32];
            while ((int)(ld_acq(fp) - need) < 0) { }
        }
        __syncwarp();

        // --- stage: warp (ks,nh) -> rows nh*8..+8, k in [96ks, 96ks+96) ---
        {
            const int row = nh * 8 + (lane >> 2);
            const int seg = lane & 3;
            const size_t sb = ((size_t)(bG0 + row) * TLEN + (t - 1)) * HD
                            + ks * 96 + seg * 24;
            const u16* sh = hhi + sb;
            const u16* sl = hlo + sb;
            char* dh = smc + OFF_AH + row * HPB + (ks * 96 + seg * 24) * 2;
            char* dl = smc + OFF_AL + row * HPB + (ks * 96 + seg * 24) * 2;
#pragma unroll
            for (int j = 0; j < 3; j++) {
                uint4 vh = __ldcg((const uint4*)(sh + j * 8));
                uint4 vl = __ldcg((const uint4*)(sl + j * 8));
                *(uint4*)(dh + j * 16) = vh;
                *(uint4*)(dl + j * 16) = vl;
            }
        }

        // gi prefetch (hidden under mma)
        float gi_r = 0.f, gi_z = 0.f, gi_n = 0.f;
        if (tid < 256) {
            const size_t xb = ((size_t)(bG0 + bg) * TLEN + t) * G3 + (u0g + ug);
            gi_r = xp[xb];
            gi_z = xp[xb + HD];
            gi_n = xp[xb + 2 * HD];
        }
        __syncthreads();

        // --- mma: m16 x (3 n-tiles) x 6 k-tiles, 3 split passes ---
        float acc[3][4];
#pragma unroll
        for (int nt = 0; nt < 3; nt++)
#pragma unroll
            for (int e = 0; e < 4; e++) acc[nt][e] = 0.f;

        const int q = lane >> 3;
        const int rq = (q & 1) * 8 + (lane & 7);
#pragma unroll
        for (int kt = 0; kt < 6; kt++) {
            const int kel = ks * 96 + kt * 16 + (q >> 1) * 8;
            unsigned ah[4], al[4];
            ldmx4(ah, sbase + OFF_AH + rq * HPB + kel * 2);
            ldmx4(al, sbase + OFF_AL + rq * HPB + kel * 2);
#pragma unroll
            for (int nt = 0; nt < 3; nt++) {
                mma16816(acc[nt], ah, bh[nt][kt]);
                mma16816(acc[nt], ah, bl[nt][kt]);
                mma16816(acc[nt], al, bh[nt][kt]);
            }
        }

        // --- dump partials: prt[ks*772 + batch*48 + rowg] ---
        {
            const int r0 = lane >> 2;
            const int c0 = (lane & 3) * 2;
            float* wp = prt + ks * 772;
#pragma unroll
            for (int nt = 0; nt < 3; nt++) {
                const int rowg = nh * 24 + nt * 8 + c0;
                *(float2*)(wp + r0 * 48 + rowg)       = make_float2(acc[nt][0], acc[nt][1]);
                *(float2*)(wp + (r0 + 8) * 48 + rowg) = make_float2(acc[nt][2], acc[nt][3]);
            }
        }
        __syncthreads();

        // --- gates (tid < 256) ---
        if (tid < 256) {
            float gh[3];
#pragma unroll
            for (int g = 0; g < 3; g++) {
                const int o = bg * 48 + g * 16 + ug;
                float s = 0.f;
#pragma unroll
                for (int k = 0; k < 8; k++) s += prt[k * 772 + o];
                gh[g] = s;
            }
            const float r = 1.f / (1.f + expf(-(gi_r + gh[0])));
            const float z = 1.f / (1.f + expf(-(gi_z + gh[1])));
            const float n = tanhf(gi_n + r * (gh[2] + bias_n));
            const float hnew = (1.f - z) * n + z * hprev;
            hprev = hnew;
            const size_t hidx = ((size_t)(bG0 + bg) * TLEN + t) * HD + (u0g + ug);
            unsigned ph = bfpk(hnew, hnew);
            float res = hnew - bflo(ph);
            unsigned pl = bfpk(res, res);
            hhi[hidx] = (u16)ph;
            hlo[hidx] = (u16)pl;
        }
        __syncthreads();

        if (tid == 0) st_rel(&g_flags[blockIdx.x * 32], flag_base + (unsigned)(t + 1));
    }
}

// ---------------------------------------------------------------------------
// Launch
// ---------------------------------------------------------------------------
extern "C" void kernel_launch(void* const* d_in, const int* in_sizes, int n_in,
                              void* d_out, int out_size)
{
    const float* features = (const float*)d_in[0];
    const float* w_ih0 = (const float*)d_in[2];
    const float* w_hh0 = (const float*)d_in[3];
    const float* b_ih0 = (const float*)d_in[4];
    const float* b_hh0 = (const float*)d_in[5];
    const float* w_ih1 = (const float*)d_in[6];
    const float* w_hh1 = (const float*)d_in[7];
    const float* b_ih1 = (const float*)d_in[8];
    const float* b_hh1 = (const float*)d_in[9];
    const float* fc_w  = (const float*)d_in[10];
    const float* fc_b  = (const float*)d_in[11];
    const float* out_w = (const float*)d_in[12];
    const float* out_b = (const float*)d_in[13];

    float *xproj, *xproj2, *fcb, *cb0, *cb1;
    u16 *fh, *fl, *hhi, *hlo, *w0h, *w0l, *w1h, *w1l, *fwh, *fwl;
    cudaGetSymbolAddress((void**)&xproj,  g_xproj);
    cudaGetSymbolAddress((void**)&xproj2, g_xproj2);
    cudaGetSymbolAddress((void**)&fcb,    g_fc);
    cudaGetSymbolAddress((void**)&cb0, g_cb0);
    cudaGetSymbolAddress((void**)&cb1, g_cb1);
    cudaGetSymbolAddress((void**)&fh,  g_fh);
    cudaGetSymbolAddress((void**)&fl,  g_fl);
    cudaGetSymbolAddress((void**)&hhi, g_hhi);
    cudaGetSymbolAddress((void**)&hlo, g_hlo);
    cudaGetSymbolAddress((void**)&w0h, g_w0h);
    cudaGetSymbolAddress((void**)&w0l, g_w0l);
    cudaGetSymbolAddress((void**)&w1h, g_w1h);
    cudaGetSymbolAddress((void**)&w1l, g_w1l);
    cudaGetSymbolAddress((void**)&fwh, g_fwh);
    cudaGetSymbolAddress((void**)&fwl, g_fwl);

    static bool attr_set = false;
    if (!attr_set) {
        cudaFuncSetAttribute(fused_layer,
                             cudaFuncAttributeMaxDynamicSharedMemorySize, (int)FUS_SMEM);
        cudaFuncSetAttribute(gemm_std,
                             cudaFuncAttributeMaxDynamicSharedMemorySize, (int)GSMEM);
        attr_set = true;
    }

    const int M = BSZ * TLEN;

    // Prep: planes + combined biases
    {
        int n4 = (BSZ * TLEN * DIN) / 4;
        pack_hl<<<(n4 + 255) / 256, 256>>>(features, fh, fl, n4);
        n4 = (G3 * DIN) / 4;
        pack_hl<<<(n4 + 255) / 256, 256>>>(w_ih0, w0h, w0l, n4);
        n4 = (G3 * HD) / 4;
        pack_hl<<<(n4 + 255) / 256, 256>>>(w_ih1, w1h, w1l, n4);
        n4 = (FCN * HD) / 4;
        pack_hl<<<(n4 + 255) / 256, 256>>>(fc_w, fwh, fwl, n4);
        combine_bias<<<(G3 + 255) / 256, 256>>>(b_ih0, b_hh0, cb0);
        combine_bias<<<(G3 + 255) / 256, 256>>>(b_ih1, b_hh1, cb1);
    }

    // xproj0 (sequential; first recurrence input)
    gemm_std<<<dim3(G3 / 64, M / 128), 256, GSMEM>>>(
        fh, fl, w0h, w0l, cb0, xproj, G3);

    // Layer 0 recurrence + xproj1 consumers (trailing)
    fused_layer<<<144, 512, FUS_SMEM>>>(
        xproj, w_hh0, b_hh0, hhi, hlo,
        hhi, hlo, w1h, w1l, cb1, xproj2, G3, 0, 0u);

    // Layer 1 recurrence + fc consumers (trailing)
    fused_layer<<<144, 512, FUS_SMEM>>>(
        xproj2, w_hh1, b_hh1, hhi, hlo,
        hhi, hlo, fwh, fwl, fc_b, fcb, FCN, 1, 1024u);

    // out_proj + tanh
    gemm_out_tanh<<<dim3(1, M / 128), 256>>>(fcb, out_w, out_b, (float*)d_out,
                                             M, NOUTC, FCN);
}

// round 16
// speedup vs baseline: 2.5315x; 1.0577x over previous
#include <cuda_runtime.h>
#include <cuda_bf16.h>
#include <math.h>

// Problem constants
#define BSZ   32
#define TLEN  1024
#define DIN   768
#define HD    768
#define G3    2304
#define FCN   512
#define NOUTC 39

typedef unsigned long long ull;
typedef unsigned short u16;

// ---------------------------------------------------------------------------
// Scratch (device globals)
// ---------------------------------------------------------------------------
__device__ float g_xproj [(size_t)BSZ * TLEN * G3];   // layer-0 input projections
__device__ float g_xproj2[(size_t)BSZ * TLEN * G3];   // layer-1 input projections
__device__ float g_fc    [(size_t)BSZ * TLEN * FCN];  // fc output
__device__ float g_cb0[G3], g_cb1[G3];                // combined biases (b_ih + b_hh[r,z])

// bf16 hi/lo planes
__device__ u16 g_fh [(size_t)BSZ * TLEN * DIN], g_fl [(size_t)BSZ * TLEN * DIN];
__device__ u16 g_hhi[(size_t)BSZ * TLEN * HD],  g_hlo[(size_t)BSZ * TLEN * HD];
__device__ u16 g_w0h[(size_t)G3 * DIN], g_w0l[(size_t)G3 * DIN];
__device__ u16 g_w1h[(size_t)G3 * HD],  g_w1l[(size_t)G3 * HD];
__device__ u16 g_fwh[(size_t)FCN * HD], g_fwl[(size_t)FCN * HD];

// Flags: monotonic. h-flags +2048/replay; cflags +8/replay (mode-1 consumers).
__device__ unsigned g_flags [96 * 32];
__device__ unsigned g_cflags[48 * 32];

// ---------------------------------------------------------------------------
// Helpers
// ---------------------------------------------------------------------------
__device__ __forceinline__ void fma2(ull& d, ull a, ull b) {
    asm("fma.rn.f32x2 %0, %1, %2, %0;" : "+l"(d) : "l"(a), "l"(b));
}
__device__ __forceinline__ ull pack2(float lo, float hi) {
    ull d; asm("mov.b64 %0, {%1, %2};" : "=l"(d) : "f"(lo), "f"(hi)); return d;
}
__device__ __forceinline__ float2 unpack2(ull v) {
    float2 r; asm("mov.b64 {%0, %1}, %2;" : "=f"(r.x), "=f"(r.y) : "l"(v)); return r;
}
__device__ __forceinline__ unsigned bfpk(float hi_src, float lo_src) {
    unsigned r;
    asm("cvt.rn.bf16x2.f32 %0, %1, %2;" : "=r"(r) : "f"(hi_src), "f"(lo_src));
    return r;
}
__device__ __forceinline__ float bflo(unsigned p) { return __uint_as_float(p << 16); }
__device__ __forceinline__ float bfhi(unsigned p) { return __uint_as_float(p & 0xFFFF0000u); }

__device__ __forceinline__ void mma16816(float* d, const unsigned* a, const unsigned* b) {
    asm volatile(
        "mma.sync.aligned.m16n8k16.row.col.f32.bf16.bf16.f32 "
        "{%0,%1,%2,%3}, {%4,%5,%6,%7}, {%8,%9}, {%0,%1,%2,%3};"
        : "+f"(d[0]), "+f"(d[1]), "+f"(d[2]), "+f"(d[3])
        : "r"(a[0]), "r"(a[1]), "r"(a[2]), "r"(a[3]), "r"(b[0]), "r"(b[1]));
}
__device__ __forceinline__ void ldmx4(unsigned* r, unsigned saddr) {
    asm volatile("ldmatrix.sync.aligned.m8n8.x4.shared.b16 {%0,%1,%2,%3}, [%4];"
                 : "=r"(r[0]), "=r"(r[1]), "=r"(r[2]), "=r"(r[3]) : "r"(saddr));
}
__device__ __forceinline__ void ldmx2(unsigned* r, unsigned saddr) {
    asm volatile("ldmatrix.sync.aligned.m8n8.x2.shared.b16 {%0,%1}, [%2];"
                 : "=r"(r[0]), "=r"(r[1]) : "r"(saddr));
}
__device__ __forceinline__ void cp16(void* smem_dst, const void* gsrc) {
    unsigned s = (unsigned)__cvta_generic_to_shared(smem_dst);
    asm volatile("cp.async.cg.shared.global [%0], [%1], 16;" :: "r"(s), "l"(gsrc));
}
__device__ __forceinline__ void cp_commit() { asm volatile("cp.async.commit_group;"); }
template <int N>
__device__ __forceinline__ void cp_wait() {
    asm volatile("cp.async.wait_group %0;" :: "n"(N));
}
__device__ __forceinline__ unsigned ld_acq(const unsigned* p) {
    unsigned v;
    asm volatile("ld.acquire.gpu.global.u32 %0, [%1];" : "=r"(v) : "l"(p) : "memory");
    return v;
}
__device__ __forceinline__ void st_rel(unsigned* p, unsigned v) {
    asm volatile("st.release.gpu.global.u32 [%0], %1;" :: "l"(p), "r"(v) : "memory");
}

// ---------------------------------------------------------------------------
// Prep kernels
// ---------------------------------------------------------------------------
__global__ __launch_bounds__(256) void pack_hl(
    const float* __restrict__ src, u16* __restrict__ dhi, u16* __restrict__ dlo, int n4)
{
    const int i = blockIdx.x * 256 + threadIdx.x;
    if (i >= n4) return;
    float4 v = ((const float4*)src)[i];
    unsigned p0 = bfpk(v.x, v.x), p1 = bfpk(v.y, v.y);
    unsigned p2 = bfpk(v.z, v.z), p3 = bfpk(v.w, v.w);
    float r0 = v.x - bflo(p0), r1 = v.y - bflo(p1);
    float r2 = v.z - bflo(p2), r3 = v.w - bflo(p3);
    unsigned q0 = bfpk(r0, r0), q1 = bfpk(r1, r1);
    unsigned q2 = bfpk(r2, r2), q3 = bfpk(r3, r3);
    ushort4 hi, lo;
    hi.x = (u16)p0; hi.y = (u16)p1; hi.z = (u16)p2; hi.w = (u16)p3;
    lo.x = (u16)q0; lo.y = (u16)q1; lo.z = (u16)q2; lo.w = (u16)q3;
    ((ushort4*)dhi)[i] = hi;
    ((ushort4*)dlo)[i] = lo;
}

__global__ __launch_bounds__(256) void combine_bias(
    const float* __restrict__ bih, const float* __restrict__ bhh, float* __restrict__ out)
{
    const int i = blockIdx.x * 256 + threadIdx.x;
    if (i < G3) out[i] = bih[i] + (i < 2 * HD ? bhh[i] : 0.f);
}

// ---------------------------------------------------------------------------
// Split-bf16 GEMM tile (device fn). BM=128, BN=64, BK=64, K=768 fixed.
// Works inside 256- or 512-thread blocks (compute gated to tid<256).
// ---------------------------------------------------------------------------
#define GP      144
#define SA_HI   0
#define SA_LO   (128 * GP)
#define SW_HI   (2 * 128 * GP)
#define SW_LO   (SW_HI + 64 * GP)
#define STAGE   (SW_LO + 64 * GP)            // 55296
#define GSMEM   (2 * STAGE)                  // 110592

__device__ __forceinline__ void gemm_tile_hl(
    char* smg, unsigned sbase,
    const u16* __restrict__ Ah, const u16* __restrict__ Al,
    const u16* __restrict__ Wh, const u16* __restrict__ Wl,
    const float* __restrict__ bias, float* __restrict__ C,
    int m0, int n0, int N, int ACT)
{
    const int tid  = threadIdx.x;
    const int warp = tid >> 5;
    const int lane = tid & 31;
    const int wm   = warp >> 1;
    const int wn   = warp & 1;
    const int lr   = (tid >> 3) & 31;
    const int lc   = tid & 7;
    const bool act25 = (tid < 256);
    const int K = 768, NS = 12;

    float acc[2][4][4];
#pragma unroll
    for (int mt = 0; mt < 2; mt++)
#pragma unroll
        for (int nt = 0; nt < 4; nt++)
#pragma unroll
            for (int e = 0; e < 4; e++) acc[mt][nt][e] = 0.f;

    const int q  = lane >> 3;
    const int rq = (q & 1) * 8 + (lane & 7);
    const int qk = q >> 1;
    const int l2 = lane & 15;
    const int brow = l2 & 7;
    const int bk16 = ((l2 >> 3) & 1) * 16;

    // slab 0
    if (act25) {
        char* st = smg;
#pragma unroll
        for (int p = 0; p < 4; p++) {
            const int r = lr + p * 32;
            cp16(st + SA_HI + r * GP + lc * 16, Ah + (size_t)(m0 + r) * K + lc * 8);
            cp16(st + SA_LO + r * GP + lc * 16, Al + (size_t)(m0 + r) * K + lc * 8);
        }
#pragma unroll
        for (int p = 0; p < 2; p++) {
            const int r = lr + p * 32;
            cp16(st + SW_HI + r * GP + lc * 16, Wh + (size_t)(n0 + r) * K + lc * 8);
            cp16(st + SW_LO + r * GP + lc * 16, Wl + (size_t)(n0 + r) * K + lc * 8);
        }
        cp_commit();
    }

    for (int s = 0; s < NS; s++) {
        if (s + 1 < NS) {
            if (act25) {
                const int k0 = (s + 1) * 64;
                char* st = smg + ((s + 1) & 1) * STAGE;
#pragma unroll
                for (int p = 0; p < 4; p++) {
                    const int r = lr + p * 32;
                    cp16(st + SA_HI + r * GP + lc * 16, Ah + (size_t)(m0 + r) * K + k0 + lc * 8);
                    cp16(st + SA_LO + r * GP + lc * 16, Al + (size_t)(m0 + r) * K + k0 + lc * 8);
                }
#pragma unroll
                for (int p = 0; p < 2; p++) {
                    const int r = lr + p * 32;
                    cp16(st + SW_HI + r * GP + lc * 16, Wh + (size_t)(n0 + r) * K + k0 + lc * 8);
                    cp16(st + SW_LO + r * GP + lc * 16, Wl + (size_t)(n0 + r) * K + k0 + lc * 8);
                }
                cp_commit();
            }
            cp_wait<1>();
        } else {
            cp_wait<0>();
        }
        __syncthreads();

        if (warp < 8) {
            const unsigned stA_hi = sbase + (s & 1) * STAGE + SA_HI;
            const unsigned stA_lo = sbase + (s & 1) * STAGE + SA_LO;
            const unsigned stW_hi = sbase + (s & 1) * STAGE + SW_HI;
            const unsigned stW_lo = sbase + (s & 1) * STAGE + SW_LO;
#pragma unroll
            for (int kt = 0; kt < 4; kt++) {
                unsigned ah[2][4], al[2][4], bh2[4][2], bl2[4][2];
#pragma unroll
                for (int mt = 0; mt < 2; mt++) {
                    const int row = wm * 32 + mt * 16 + rq;
                    ldmx4(ah[mt], stA_hi + row * GP + kt * 32 + qk * 16);
                    ldmx4(al[mt], stA_lo + row * GP + kt * 32 + qk * 16);
                }
#pragma unroll
                for (int nt = 0; nt < 4; nt++) {
                    const int row = wn * 32 + nt * 8 + brow;
                    ldmx2(bh2[nt], stW_hi + row * GP + kt * 32 + bk16);
                    ldmx2(bl2[nt], stW_lo + row * GP + kt * 32 + bk16);
                }
#pragma unroll
                for (int mt = 0; mt < 2; mt++)
#pragma unroll
                    for (int nt = 0; nt < 4; nt++) {
                        mma16816(acc[mt][nt], ah[mt], bh2[nt]);
                        mma16816(acc[mt][nt], ah[mt], bl2[nt]);
                        mma16816(acc[mt][nt], al[mt], bh2[nt]);
                    }
            }
        }
        __syncthreads();
    }

    if (warp < 8) {
        const float selu_scale = 1.0507009873554804934193349852946f;
        const float selu_alpha = 1.6732632423543772848170429916717f;
        const int r0 = lane >> 2;
        const int c0 = (lane & 3) * 2;
#pragma unroll
        for (int mt = 0; mt < 2; mt++)
#pragma unroll
            for (int nt = 0; nt < 4; nt++) {
                const int col = n0 + wn * 32 + nt * 8 + c0;
                const float b0 = bias[col], b1 = bias[col + 1];
#pragma unroll
                for (int h = 0; h < 2; h++) {
                    const int row = m0 + wm * 32 + mt * 16 + r0 + h * 8;
                    float v0 = acc[mt][nt][h * 2 + 0] + b0;
                    float v1 = acc[mt][nt][h * 2 + 1] + b1;
                    if (ACT == 1) {
                        v0 = selu_scale * (v0 > 0.f ? v0 : selu_alpha * (expf(v0) - 1.f));
                        v1 = selu_scale * (v1 > 0.f ? v1 : selu_alpha * (expf(v1) - 1.f));
                    }
                    *(float2*)(C + (size_t)row * N + col) = make_float2(v0, v1);
                }
            }
    }
}

// Standalone GEMM (xproj0)
__global__ __launch_bounds__(256) void gemm_std(
    const u16* __restrict__ Ah, const u16* __restrict__ Al,
    const u16* __restrict__ Wh, const u16* __restrict__ Wl,
    const float* __restrict__ bias, float* __restrict__ C, int N)
{
    extern __shared__ char smg[];
    unsigned sbase;
    asm("{ .reg .u64 t; cvta.to.shared.u64 t, %1; cvt.u32.u64 %0, t; }"
        : "=r"(sbase) : "l"(smg));
    gemm_tile_hl(smg, sbase, Ah, Al, Wh, Wl, bias, C,
                 blockIdx.y * 128, blockIdx.x * 64, N, 0);
}

// ---------------------------------------------------------------------------
// out_proj tile (device fn, fp32 FFMA2): 128 rows x 39 cols, K=FCN=512.
// 512-thread-safe: compute gated to tid<256, all threads hit syncthreads.
// smem: uses first 8192 B of the dynamic smem region.
// ---------------------------------------------------------------------------
__device__ __forceinline__ void out_tile(
    char* smg, const float* __restrict__ A, const float* __restrict__ W,
    const float* __restrict__ bias, float* __restrict__ C, int m0)
{
    float (*As)[128] = (float(*)[128])smg;
    float (*Bs)[128] = (float(*)[128])(smg + 4096);

    const int tid  = threadIdx.x;
    const bool act = (tid < 256);
    const int lrow = (tid & 255) >> 1;
    const int lk4  = (tid & 1) * 4;
    const int tx = tid & 15;
    const int ty = (tid & 255) >> 4;

    ull acc2[8][4];
#pragma unroll
    for (int i = 0; i < 8; i++)
#pragma unroll
        for (int j = 0; j < 4; j++) acc2[i][j] = 0ull;

    const float* Arow = A + (size_t)(m0 + lrow) * FCN + lk4;
    const float* Wrow = W + (size_t)lrow * FCN + lk4;
    const bool   wok  = act && (lrow < NOUTC);

    for (int k0 = 0; k0 < FCN; k0 += 8) {
        float4 av = make_float4(0.f, 0.f, 0.f, 0.f);
        float4 wv = make_float4(0.f, 0.f, 0.f, 0.f);
        if (act) av = *(const float4*)(Arow + k0);
        if (wok) wv = *(const float4*)(Wrow + k0);

        __syncthreads();
        if (act) {
            As[lk4 + 0][lrow] = av.x; As[lk4 + 1][lrow] = av.y;
            As[lk4 + 2][lrow] = av.z; As[lk4 + 3][lrow] = av.w;
            Bs[lk4 + 0][lrow] = wv.x; Bs[lk4 + 1][lrow] = wv.y;
            Bs[lk4 + 2][lrow] = wv.z; Bs[lk4 + 3][lrow] = wv.w;
        }
        __syncthreads();

        if (act) {
#pragma unroll
            for (int kk = 0; kk < 8; kk++) {
                float a[8];
                *(float4*)(a)     = *(const float4*)&As[kk][ty * 4];
                *(float4*)(a + 4) = *(const float4*)&As[kk][64 + ty * 4];
                ulonglong2 b01 = *(const ulonglong2*)&Bs[kk][tx * 4];
                ulonglong2 b23 = *(const ulonglong2*)&Bs[kk][64 + tx * 4];
                ull bb[4] = { b01.x, b01.y, b23.x, b23.y };
                ull aa[8];
#pragma unroll
                for (int i = 0; i < 8; i++) aa[i] = pack2(a[i], a[i]);
#pragma unroll
                for (int i = 0; i < 8; i++)
#pragma unroll
                    for (int j = 0; j < 4; j++)
                        fma2(acc2[i][j], aa[i], bb[j]);
            }
        }
    }

    if (act) {
#pragma unroll
        for (int i = 0; i < 8; i++) {
            const int m = m0 + ((i < 4) ? (ty * 4 + i) : (64 + ty * 4 + i - 4));
            float* crow = C + (size_t)m * NOUTC;
#pragma unroll
            for (int j = 0; j < 4; j++) {
                const int nf = (j < 2) ? (tx * 4 + j * 2) : (64 + tx * 4 + (j - 2) * 2);
                float2 v = unpack2(acc2[i][j]);
                float vals[2] = { v.x, v.y };
#pragma unroll
                for (int s = 0; s < 2; s++) {
                    const int n = nf + s;
                    if (n < NOUTC) crow[n] = tanhf(vals[s] + bias[n]);
                }
            }
        }
    }
}

// ---------------------------------------------------------------------------
// Fused persistent kernel: blocks 0-95 = GRU recurrence (2 batch groups x 48),
// blocks 96-143 = trailing FF-GEMM consumers.
// Recurrence block: 512 threads, 16 units, warp=(k-slice 0..7, n-half 0..1),
// B-frags register-resident, m16 A tile = the group's 16 batches.
// Mode-1 consumers additionally compute out_proj per fc chunk (cflag-synced).
// ---------------------------------------------------------------------------
#define HPB      1552
#define OFF_AH   0
#define OFF_AL   24832                       // 16*1552
#define OFF_PRT  49664                       // floats from here: 8*772
#define SCR_HI   0                           // init-only W scratch (24*1552)
#define SCR_LO   37248
#define FUS_SMEM GSMEM                       // 110592 (covers both roles)

__global__ __launch_bounds__(512, 1) void fused_layer(
    const float* __restrict__ xp,            // [B,T,3H] (combined bias folded for r,z)
    const float* __restrict__ w_hh,          // [3H,H] fp32
    const float* __restrict__ b_hh,          // [3H] (n-gate bias used)
    u16* __restrict__ hhi, u16* __restrict__ hlo,
    const u16* __restrict__ cAh, const u16* __restrict__ cAl,
    const u16* __restrict__ cWh, const u16* __restrict__ cWl,
    const float* __restrict__ cbias, float* __restrict__ cC,
    int cN, int cACT, unsigned base_off,
    const float* __restrict__ outw,          // out_proj weight (mode 1 only)
    const float* __restrict__ outb,          // out_proj bias   (mode 1 only)
    float* __restrict__ outp)                // d_out           (mode 1 only)
{
    extern __shared__ char smc[];
    unsigned sbase;
    asm("{ .reg .u64 t; cvta.to.shared.u64 t, %1; cvt.u32.u64 %0, t; }"
        : "=r"(sbase) : "l"(smc));
    const int tid = threadIdx.x;

    // ======================= CONSUMER BLOCKS =======================
    if (blockIdx.x >= 96) {
        const int cid = blockIdx.x - 96;
        const unsigned f = ld_acq(&g_flags[0]);
        const unsigned base = (f / 2048u) * 2048u + base_off;
        const int tnt = cN / 64;
        const unsigned cb = outp ? ld_acq(&g_cflags[cid * 32]) : 0u;

        for (int tc = 0; tc < 8; tc++) {
            const unsigned target = base + (unsigned)((tc + 1) * 128);
            if (tid < 96) {
                while ((int)(ld_acq(&g_flags[tid * 32]) - target) < 0) { }
            }
            __syncthreads();
            for (int i = cid; i < 32 * tnt; i += 48) {
                const int b  = i / tnt;
                const int nt = i % tnt;
                gemm_tile_hl(smc, sbase, cAh, cAl, cWh, cWl, cbias, cC,
                             b * TLEN + tc * 128, nt * 64, cN, cACT);
            }

            // ---- mode-1 trailing out_proj for this chunk ----
            if (outp) {
                __syncthreads();                     // all fc stores of this block issued
                if (tid == 0)
                    st_rel(&g_cflags[cid * 32], cb + (unsigned)(tc + 1));
                const unsigned ctar = cb + (unsigned)(tc + 1);
                if (tid < 48) {
                    while ((int)(ld_acq(&g_cflags[tid * 32]) - ctar) < 0) { }
                }
                __syncthreads();                     // fc of chunk tc globally complete
                for (int b = cid; b < 32; b += 48)
                    out_tile(smc, cC, outw, outb, outp, b * TLEN + tc * 128);
                __syncthreads();                     // smem reuse barrier
            }
        }
        return;
    }

    // ======================= RECURRENCE BLOCKS =======================
    const int grp  = blockIdx.x / 48;        // batch group (16 batches)
    const int ub   = blockIdx.x % 48;
    const int u0g  = ub * 16;                // unit base
    const int bG0  = grp * 16;               // batch base
    const int warp = tid >> 5;
    const int lane = tid & 31;
    const int ks   = warp >> 1;              // k-slice 0..7 (96 wide)
    const int nh   = warp & 1;               // n-half 0..1 (24 rows)
    const unsigned flag_base = g_flags[blockIdx.x * 32];

    // ---- W init: 2 passes through scratch; frags -> registers ----
    unsigned bh[3][6][2], bl[3][6][2];
    for (int p = 0; p < 2; p++) {
        for (int i = tid; i < 24 * 96; i += 512) {
            const int r  = i / 96;            // scratch row 0..23
            const int kc = (i % 96) * 8;
            const int rg = p * 24 + r;        // gh row 0..47 (gate*16+unit)
            const int gate = rg >> 4, ul = rg & 15;
            const float* ws = w_hh + (size_t)(gate * HD + u0g + ul) * HD + kc;
            float4 a = *(const float4*)(ws);
            float4 b = *(const float4*)(ws + 4);
            unsigned h0 = bfpk(a.y, a.x), h1 = bfpk(a.w, a.z);
            unsigned h2 = bfpk(b.y, b.x), h3 = bfpk(b.w, b.z);
            unsigned l0 = bfpk(a.y - bfhi(h0), a.x - bflo(h0));
            unsigned l1 = bfpk(a.w - bfhi(h1), a.z - bflo(h1));
            unsigned l2_ = bfpk(b.y - bfhi(h2), b.x - bflo(h2));
            unsigned l3 = bfpk(b.w - bfhi(h3), b.z - bflo(h3));
            *(uint4*)(smc + SCR_HI + r * HPB + kc * 2) = make_uint4(h0, h1, h2, h3);
            *(uint4*)(smc + SCR_LO + r * HPB + kc * 2) = make_uint4(l0, l1, l2_, l3);
        }
        __syncthreads();
        if (nh == p) {
            const int l2 = lane & 15;
#pragma unroll
            for (int nt = 0; nt < 3; nt++)
#pragma unroll
                for (int kt = 0; kt < 6; kt++) {
                    const int row = nt * 8 + (l2 & 7);
                    const int kel = ks * 96 + kt * 16 + ((l2 >> 3) & 1) * 8;
                    ldmx2(bh[nt][kt], sbase + SCR_HI + row * HPB + kel * 2);
                    ldmx2(bl[nt][kt], sbase + SCR_LO + row * HPB + kel * 2);
                }
        }
        __syncthreads();
    }

    // ---- gate decode (tid < 256) ----
    const int bg = tid >> 4;                 // local batch 0..15
    const int ug = tid & 15;                 // local unit 0..15
    float bias_n = 0.f, hprev = 0.f;
    if (tid < 256) bias_n = b_hh[2 * HD + u0g + ug];

    // ---- t = 0: gh = 0 (biases folded into xp for r,z) ----
    if (tid < 256) {
        const size_t xb = ((size_t)(bG0 + bg) * TLEN + 0) * G3 + (u0g + ug);
        const float gi_r = xp[xb];
        const float gi_z = xp[xb + HD];
        const float gi_n = xp[xb + 2 * HD];
        const float r = 1.f / (1.f + expf(-gi_r));
        const float z = 1.f / (1.f + expf(-gi_z));
        const float n = tanhf(gi_n + r * bias_n);
        hprev = (1.f - z) * n;
        const size_t hidx = ((size_t)(bG0 + bg) * TLEN + 0) * HD + (u0g + ug);
        unsigned ph = bfpk(hprev, hprev);
        float res = hprev - bflo(ph);
        unsigned pl = bfpk(res, res);
        hhi[hidx] = (u16)ph;
        hlo[hidx] = (u16)pl;
    }
    __syncthreads();
    if (tid == 0) st_rel(&g_flags[blockIdx.x * 32], flag_base + 1u);

    float* prt = (float*)(smc + OFF_PRT);

    for (int t = 1; t < TLEN; t++) {
        // --- poll: 6 source blocks for this warp's k-slice ---
        const unsigned need = flag_base + (unsigned)t;
        if (lane < 6) {
            const unsigned* fp = &g_flags[(grp * 48 + ks * 6 + lane) * 32];
            while ((int)(ld_acq(fp) - need) < 0) { }
        }
        __syncwarp();

        // --- stage: warp (ks,nh) -> rows nh*8..+8, k in [96ks, 96ks+96) ---
        {
            const int row = nh * 8 + (lane >> 2);
            const int seg = lane & 3;
            const size_t sb = ((size_t)(bG0 + row) * TLEN + (t - 1)) * HD
                            + ks * 96 + seg * 24;
            const u16* sh = hhi + sb;
            const u16* sl = hlo + sb;
            char* dh = smc + OFF_AH + row * HPB + (ks * 96 + seg * 24) * 2;
            char* dl = smc + OFF_AL + row * HPB + (ks * 96 + seg * 24) * 2;
#pragma unroll
            for (int j = 0; j < 3; j++) {
                uint4 vh = __ldcg((const uint4*)(sh + j * 8));
                uint4 vl = __ldcg((const uint4*)(sl + j * 8));
                *(uint4*)(dh + j * 16) = vh;
                *(uint4*)(dl + j * 16) = vl;
            }
        }

        // gi prefetch (hidden under mma)
        float gi_r = 0.f, gi_z = 0.f, gi_n = 0.f;
        if (tid < 256) {
            const size_t xb = ((size_t)(bG0 + bg) * TLEN + t) * G3 + (u0g + ug);
            gi_r = xp[xb];
            gi_z = xp[xb + HD];
            gi_n = xp[xb + 2 * HD];
        }
        __syncthreads();

        // --- mma: m16 x (3 n-tiles) x 6 k-tiles, 3 split passes ---
        float acc[3][4];
#pragma unroll
        for (int nt = 0; nt < 3; nt++)
#pragma unroll
            for (int e = 0; e < 4; e++) acc[nt][e] = 0.f;

        const int q = lane >> 3;
        const int rq = (q & 1) * 8 + (lane & 7);
#pragma unroll
        for (int kt = 0; kt < 6; kt++) {
            const int kel = ks * 96 + kt * 16 + (q >> 1) * 8;
            unsigned ah[4], al[4];
            ldmx4(ah, sbase + OFF_AH + rq * HPB + kel * 2);
            ldmx4(al, sbase + OFF_AL + rq * HPB + kel * 2);
#pragma unroll
            for (int nt = 0; nt < 3; nt++) {
                mma16816(acc[nt], ah, bh[nt][kt]);
                mma16816(acc[nt], ah, bl[nt][kt]);
                mma16816(acc[nt], al, bh[nt][kt]);
            }
        }

        // --- dump partials: prt[ks*772 + batch*48 + rowg] ---
        {
            const int r0 = lane >> 2;
            const int c0 = (lane & 3) * 2;
            float* wp = prt + ks * 772;
#pragma unroll
            for (int nt = 0; nt < 3; nt++) {
                const int rowg = nh * 24 + nt * 8 + c0;
                *(float2*)(wp + r0 * 48 + rowg)       = make_float2(acc[nt][0], acc[nt][1]);
                *(float2*)(wp + (r0 + 8) * 48 + rowg) = make_float2(acc[nt][2], acc[nt][3]);
            }
        }
        __syncthreads();

        // --- gates (tid < 256) ---
        if (tid < 256) {
            float gh[3];
#pragma unroll
            for (int g = 0; g < 3; g++) {
                const int o = bg * 48 + g * 16 + ug;
                float s = 0.f;
#pragma unroll
                for (int k = 0; k < 8; k++) s += prt[k * 772 + o];
                gh[g] = s;
            }
            const float r = 1.f / (1.f + expf(-(gi_r + gh[0])));
            const float z = 1.f / (1.f + expf(-(gi_z + gh[1])));
            const float n = tanhf(gi_n + r * (gh[2] + bias_n));
            const float hnew = (1.f - z) * n + z * hprev;
            hprev = hnew;
            const size_t hidx = ((size_t)(bG0 + bg) * TLEN + t) * HD + (u0g + ug);
            unsigned ph = bfpk(hnew, hnew);
            float res = hnew - bflo(ph);
            unsigned pl = bfpk(res, res);
            hhi[hidx] = (u16)ph;
            hlo[hidx] = (u16)pl;
        }
        __syncthreads();

        if (tid == 0) st_rel(&g_flags[blockIdx.x * 32], flag_base + (unsigned)(t + 1));
    }
}

// ---------------------------------------------------------------------------
// Launch: 9 graph nodes (out_proj fused into launch 2).
// ---------------------------------------------------------------------------
extern "C" void kernel_launch(void* const* d_in, const int* in_sizes, int n_in,
                              void* d_out, int out_size)
{
    const float* features = (const float*)d_in[0];
    const float* w_ih0 = (const float*)d_in[2];
    const float* w_hh0 = (const float*)d_in[3];
    const float* b_ih0 = (const float*)d_in[4];
    const float* b_hh0 = (const float*)d_in[5];
    const float* w_ih1 = (const float*)d_in[6];
    const float* w_hh1 = (const float*)d_in[7];
    const float* b_ih1 = (const float*)d_in[8];
    const float* b_hh1 = (const float*)d_in[9];
    const float* fc_w  = (const float*)d_in[10];
    const float* fc_b  = (const float*)d_in[11];
    const float* out_w = (const float*)d_in[12];
    const float* out_b = (const float*)d_in[13];

    float *xproj, *xproj2, *fcb, *cb0, *cb1;
    u16 *fh, *fl, *hhi, *hlo, *w0h, *w0l, *w1h, *w1l, *fwh, *fwl;
    cudaGetSymbolAddress((void**)&xproj,  g_xproj);
    cudaGetSymbolAddress((void**)&xproj2, g_xproj2);
    cudaGetSymbolAddress((void**)&fcb,    g_fc);
    cudaGetSymbolAddress((void**)&cb0, g_cb0);
    cudaGetSymbolAddress((void**)&cb1, g_cb1);
    cudaGetSymbolAddress((void**)&fh,  g_fh);
    cudaGetSymbolAddress((void**)&fl,  g_fl);
    cudaGetSymbolAddress((void**)&hhi, g_hhi);
    cudaGetSymbolAddress((void**)&hlo, g_hlo);
    cudaGetSymbolAddress((void**)&w0h, g_w0h);
    cudaGetSymbolAddress((void**)&w0l, g_w0l);
    cudaGetSymbolAddress((void**)&w1h, g_w1h);
    cudaGetSymbolAddress((void**)&w1l, g_w1l);
    cudaGetSymbolAddress((void**)&fwh, g_fwh);
    cudaGetSymbolAddress((void**)&fwl, g_fwl);

    static bool attr_set = false;
    if (!attr_set) {
        cudaFuncSetAttribute(fused_layer,
                             cudaFuncAttributeMaxDynamicSharedMemorySize, (int)FUS_SMEM);
        cudaFuncSetAttribute(gemm_std,
                             cudaFuncAttributeMaxDynamicSharedMemorySize, (int)GSMEM);
        attr_set = true;
    }

    const int M = BSZ * TLEN;

    // Prep: planes + combined biases
    {
        int n4 = (BSZ * TLEN * DIN) / 4;
        pack_hl<<<(n4 + 255) / 256, 256>>>(features, fh, fl, n4);
        n4 = (G3 * DIN) / 4;
        pack_hl<<<(n4 + 255) / 256, 256>>>(w_ih0, w0h, w0l, n4);
        n4 = (G3 * HD) / 4;
        pack_hl<<<(n4 + 255) / 256, 256>>>(w_ih1, w1h, w1l, n4);
        n4 = (FCN * HD) / 4;
        pack_hl<<<(n4 + 255) / 256, 256>>>(fc_w, fwh, fwl, n4);
        combine_bias<<<(G3 + 255) / 256, 256>>>(b_ih0, b_hh0, cb0);
        combine_bias<<<(G3 + 255) / 256, 256>>>(b_ih1, b_hh1, cb1);
    }

    // xproj0 (sequential; first recurrence input)
    gemm_std<<<dim3(G3 / 64, M / 128), 256, GSMEM>>>(
        fh, fl, w0h, w0l, cb0, xproj, G3);

    // Layer 0 recurrence + xproj1 consumers (trailing)
    fused_layer<<<144, 512, FUS_SMEM>>>(
        xproj, w_hh0, b_hh0, hhi, hlo,
        hhi, hlo, w1h, w1l, cb1, xproj2, G3, 0, 0u,
        nullptr, nullptr, nullptr);

    // Layer 1 recurrence + fc consumers + trailing out_proj
    fused_layer<<<144, 512, FUS_SMEM>>>(
        xproj2, w_hh1, b_hh1, hhi, hlo,
        hhi, hlo, fwh, fwl, fc_b, fcb, FCN, 1, 1024u,
        out_w, out_b, (float*)d_out);
}

// round 17
// speedup vs baseline: 2.5871x; 1.0220x over previous
#include <cuda_runtime.h>
#include <cuda_bf16.h>
#include <math.h>

// Problem constants
#define BSZ   32
#define TLEN  1024
#define DIN   768
#define HD    768
#define G3    2304
#define FCN   512
#define NOUTC 39

typedef unsigned long long ull;
typedef unsigned short u16;

// ---------------------------------------------------------------------------
// Scratch (device globals)
// ---------------------------------------------------------------------------
__device__ float g_xproj [(size_t)BSZ * TLEN * G3];   // layer-0 input projections
__device__ float g_xproj2[(size_t)BSZ * TLEN * G3];   // layer-1 input projections
__device__ float g_fc    [(size_t)BSZ * TLEN * FCN];  // fc output
__device__ float g_cb0[G3], g_cb1[G3];                // combined biases (b_ih + b_hh[r,z])

// bf16 hi/lo planes
__device__ u16 g_fh [(size_t)BSZ * TLEN * DIN], g_fl [(size_t)BSZ * TLEN * DIN];
__device__ u16 g_hhi[(size_t)BSZ * TLEN * HD],  g_hlo[(size_t)BSZ * TLEN * HD];
__device__ u16 g_w0h[(size_t)G3 * DIN], g_w0l[(size_t)G3 * DIN];
__device__ u16 g_w1h[(size_t)G3 * HD],  g_w1l[(size_t)G3 * HD];
__device__ u16 g_fwh[(size_t)FCN * HD], g_fwl[(size_t)FCN * HD];

// Flags: monotonic. h-flags +2048/replay; cflags +10/replay (mode-1 consumers:
// 2 leading xproj1 chunks + 8 fc chunks).
__device__ unsigned g_flags [96 * 32];
__device__ unsigned g_cflags[48 * 32];

// ---------------------------------------------------------------------------
// Helpers
// ---------------------------------------------------------------------------
__device__ __forceinline__ void fma2(ull& d, ull a, ull b) {
    asm("fma.rn.f32x2 %0, %1, %2, %0;" : "+l"(d) : "l"(a), "l"(b));
}
__device__ __forceinline__ ull pack2(float lo, float hi) {
    ull d; asm("mov.b64 %0, {%1, %2};" : "=l"(d) : "f"(lo), "f"(hi)); return d;
}
__device__ __forceinline__ float2 unpack2(ull v) {
    float2 r; asm("mov.b64 {%0, %1}, %2;" : "=f"(r.x), "=f"(r.y) : "l"(v)); return r;
}
__device__ __forceinline__ unsigned bfpk(float hi_src, float lo_src) {
    unsigned r;
    asm("cvt.rn.bf16x2.f32 %0, %1, %2;" : "=r"(r) : "f"(hi_src), "f"(lo_src));
    return r;
}
__device__ __forceinline__ float bflo(unsigned p) { return __uint_as_float(p << 16); }
__device__ __forceinline__ float bfhi(unsigned p) { return __uint_as_float(p & 0xFFFF0000u); }

__device__ __forceinline__ void mma16816(float* d, const unsigned* a, const unsigned* b) {
    asm volatile(
        "mma.sync.aligned.m16n8k16.row.col.f32.bf16.bf16.f32 "
        "{%0,%1,%2,%3}, {%4,%5,%6,%7}, {%8,%9}, {%0,%1,%2,%3};"
        : "+f"(d[0]), "+f"(d[1]), "+f"(d[2]), "+f"(d[3])
        : "r"(a[0]), "r"(a[1]), "r"(a[2]), "r"(a[3]), "r"(b[0]), "r"(b[1]));
}
__device__ __forceinline__ void ldmx4(unsigned* r, unsigned saddr) {
    asm volatile("ldmatrix.sync.aligned.m8n8.x4.shared.b16 {%0,%1,%2,%3}, [%4];"
                 : "=r"(r[0]), "=r"(r[1]), "=r"(r[2]), "=r"(r[3]) : "r"(saddr));
}
__device__ __forceinline__ void ldmx2(unsigned* r, unsigned saddr) {
    asm volatile("ldmatrix.sync.aligned.m8n8.x2.shared.b16 {%0,%1}, [%2];"
                 : "=r"(r[0]), "=r"(r[1]) : "r"(saddr));
}
__device__ __forceinline__ void cp16(void* smem_dst, const void* gsrc) {
    unsigned s = (unsigned)__cvta_generic_to_shared(smem_dst);
    asm volatile("cp.async.cg.shared.global [%0], [%1], 16;" :: "r"(s), "l"(gsrc));
}
__device__ __forceinline__ void cp_commit() { asm volatile("cp.async.commit_group;"); }
template <int N>
__device__ __forceinline__ void cp_wait() {
    asm volatile("cp.async.wait_group %0;" :: "n"(N));
}
__device__ __forceinline__ unsigned ld_acq(const unsigned* p) {
    unsigned v;
    asm volatile("ld.acquire.gpu.global.u32 %0, [%1];" : "=r"(v) : "l"(p) : "memory");
    return v;
}
__device__ __forceinline__ void st_rel(unsigned* p, unsigned v) {
    asm volatile("st.release.gpu.global.u32 [%0], %1;" :: "l"(p), "r"(v) : "memory");
}

// ---------------------------------------------------------------------------
// Prep kernels
// ---------------------------------------------------------------------------
__global__ __launch_bounds__(256) void pack_hl(
    const float* __restrict__ src, u16* __restrict__ dhi, u16* __restrict__ dlo, int n4)
{
    const int i = blockIdx.x * 256 + threadIdx.x;
    if (i >= n4) return;
    float4 v = ((const float4*)src)[i];
    unsigned p0 = bfpk(v.x, v.x), p1 = bfpk(v.y, v.y);
    unsigned p2 = bfpk(v.z, v.z), p3 = bfpk(v.w, v.w);
    float r0 = v.x - bflo(p0), r1 = v.y - bflo(p1);
    float r2 = v.z - bflo(p2), r3 = v.w - bflo(p3);
    unsigned q0 = bfpk(r0, r0), q1 = bfpk(r1, r1);
    unsigned q2 = bfpk(r2, r2), q3 = bfpk(r3, r3);
    ushort4 hi, lo;
    hi.x = (u16)p0; hi.y = (u16)p1; hi.z = (u16)p2; hi.w = (u16)p3;
    lo.x = (u16)q0; lo.y = (u16)q1; lo.z = (u16)q2; lo.w = (u16)q3;
    ((ushort4*)dhi)[i] = hi;
    ((ushort4*)dlo)[i] = lo;
}

__global__ __launch_bounds__(256) void combine_bias(
    const float* __restrict__ bih, const float* __restrict__ bhh, float* __restrict__ out)
{
    const int i = blockIdx.x * 256 + threadIdx.x;
    if (i < G3) out[i] = bih[i] + (i < 2 * HD ? bhh[i] : 0.f);
}

// ---------------------------------------------------------------------------
// Split-bf16 GEMM tile (device fn). BM=128, BN=64, BK=64, K=768 fixed.
// Works inside 256- or 512-thread blocks (compute gated to tid<256).
// ---------------------------------------------------------------------------
#define GP      144
#define SA_HI   0
#define SA_LO   (128 * GP)
#define SW_HI   (2 * 128 * GP)
#define SW_LO   (SW_HI + 64 * GP)
#define STAGE   (SW_LO + 64 * GP)            // 55296
#define GSMEM   (2 * STAGE)                  // 110592

__device__ __forceinline__ void gemm_tile_hl(
    char* smg, unsigned sbase,
    const u16* __restrict__ Ah, const u16* __restrict__ Al,
    const u16* __restrict__ Wh, const u16* __restrict__ Wl,
    const float* __restrict__ bias, float* __restrict__ C,
    int m0, int n0, int N, int ACT)
{
    const int tid  = threadIdx.x;
    const int warp = tid >> 5;
    const int lane = tid & 31;
    const int wm   = warp >> 1;
    const int wn   = warp & 1;
    const int lr   = (tid >> 3) & 31;
    const int lc   = tid & 7;
    const bool act25 = (tid < 256);
    const int K = 768, NS = 12;

    float acc[2][4][4];
#pragma unroll
    for (int mt = 0; mt < 2; mt++)
#pragma unroll
        for (int nt = 0; nt < 4; nt++)
#pragma unroll
            for (int e = 0; e < 4; e++) acc[mt][nt][e] = 0.f;

    const int q  = lane >> 3;
    const int rq = (q & 1) * 8 + (lane & 7);
    const int qk = q >> 1;
    const int l2 = lane & 15;
    const int brow = l2 & 7;
    const int bk16 = ((l2 >> 3) & 1) * 16;

    // slab 0
    if (act25) {
        char* st = smg;
#pragma unroll
        for (int p = 0; p < 4; p++) {
            const int r = lr + p * 32;
            cp16(st + SA_HI + r * GP + lc * 16, Ah + (size_t)(m0 + r) * K + lc * 8);
            cp16(st + SA_LO + r * GP + lc * 16, Al + (size_t)(m0 + r) * K + lc * 8);
        }
#pragma unroll
        for (int p = 0; p < 2; p++) {
            const int r = lr + p * 32;
            cp16(st + SW_HI + r * GP + lc * 16, Wh + (size_t)(n0 + r) * K + lc * 8);
            cp16(st + SW_LO + r * GP + lc * 16, Wl + (size_t)(n0 + r) * K + lc * 8);
        }
        cp_commit();
    }

    for (int s = 0; s < NS; s++) {
        if (s + 1 < NS) {
            if (act25) {
                const int k0 = (s + 1) * 64;
                char* st = smg + ((s + 1) & 1) * STAGE;
#pragma unroll
                for (int p = 0; p < 4; p++) {
                    const int r = lr + p * 32;
                    cp16(st + SA_HI + r * GP + lc * 16, Ah + (size_t)(m0 + r) * K + k0 + lc * 8);
                    cp16(st + SA_LO + r * GP + lc * 16, Al + (size_t)(m0 + r) * K + k0 + lc * 8);
                }
#pragma unroll
                for (int p = 0; p < 2; p++) {
                    const int r = lr + p * 32;
                    cp16(st + SW_HI + r * GP + lc * 16, Wh + (size_t)(n0 + r) * K + k0 + lc * 8);
                    cp16(st + SW_LO + r * GP + lc * 16, Wl + (size_t)(n0 + r) * K + k0 + lc * 8);
                }
                cp_commit();
            }
            cp_wait<1>();
        } else {
            cp_wait<0>();
        }
        __syncthreads();

        if (warp < 8) {
            const unsigned stA_hi = sbase + (s & 1) * STAGE + SA_HI;
            const unsigned stA_lo = sbase + (s & 1) * STAGE + SA_LO;
            const unsigned stW_hi = sbase + (s & 1) * STAGE + SW_HI;
            const unsigned stW_lo = sbase + (s & 1) * STAGE + SW_LO;
#pragma unroll
            for (int kt = 0; kt < 4; kt++) {
                unsigned ah[2][4], al[2][4], bh2[4][2], bl2[4][2];
#pragma unroll
                for (int mt = 0; mt < 2; mt++) {
                    const int row = wm * 32 + mt * 16 + rq;
                    ldmx4(ah[mt], stA_hi + row * GP + kt * 32 + qk * 16);
                    ldmx4(al[mt], stA_lo + row * GP + kt * 32 + qk * 16);
                }
#pragma unroll
                for (int nt = 0; nt < 4; nt++) {
                    const int row = wn * 32 + nt * 8 + brow;
                    ldmx2(bh2[nt], stW_hi + row * GP + kt * 32 + bk16);
                    ldmx2(bl2[nt], stW_lo + row * GP + kt * 32 + bk16);
                }
#pragma unroll
                for (int mt = 0; mt < 2; mt++)
#pragma unroll
                    for (int nt = 0; nt < 4; nt++) {
                        mma16816(acc[mt][nt], ah[mt], bh2[nt]);
                        mma16816(acc[mt][nt], ah[mt], bl2[nt]);
                        mma16816(acc[mt][nt], al[mt], bh2[nt]);
                    }
            }
        }
        __syncthreads();
    }

    if (warp < 8) {
        const float selu_scale = 1.0507009873554804934193349852946f;
        const float selu_alpha = 1.6732632423543772848170429916717f;
        const int r0 = lane >> 2;
        const int c0 = (lane & 3) * 2;
#pragma unroll
        for (int mt = 0; mt < 2; mt++)
#pragma unroll
            for (int nt = 0; nt < 4; nt++) {
                const int col = n0 + wn * 32 + nt * 8 + c0;
                const float b0 = bias[col], b1 = bias[col + 1];
#pragma unroll
                for (int h = 0; h < 2; h++) {
                    const int row = m0 + wm * 32 + mt * 16 + r0 + h * 8;
                    float v0 = acc[mt][nt][h * 2 + 0] + b0;
                    float v1 = acc[mt][nt][h * 2 + 1] + b1;
                    if (ACT == 1) {
                        v0 = selu_scale * (v0 > 0.f ? v0 : selu_alpha * (expf(v0) - 1.f));
                        v1 = selu_scale * (v1 > 0.f ? v1 : selu_alpha * (expf(v1) - 1.f));
                    }
                    *(float2*)(C + (size_t)row * N + col) = make_float2(v0, v1);
                }
            }
    }
}

// Standalone GEMM (xproj0)
__global__ __launch_bounds__(256) void gemm_std(
    const u16* __restrict__ Ah, const u16* __restrict__ Al,
    const u16* __restrict__ Wh, const u16* __restrict__ Wl,
    const float* __restrict__ bias, float* __restrict__ C, int N)
{
    extern __shared__ char smg[];
    unsigned sbase;
    asm("{ .reg .u64 t; cvta.to.shared.u64 t, %1; cvt.u32.u64 %0, t; }"
        : "=r"(sbase) : "l"(smg));
    gemm_tile_hl(smg, sbase, Ah, Al, Wh, Wl, bias, C,
                 blockIdx.y * 128, blockIdx.x * 64, N, 0);
}

// ---------------------------------------------------------------------------
// out_proj tile (device fn, fp32 FFMA2): 128 rows x 39 cols, K=FCN=512.
// 512-thread-safe: compute gated to tid<256, all threads hit syncthreads.
// ---------------------------------------------------------------------------
__device__ __forceinline__ void out_tile(
    char* smg, const float* __restrict__ A, const float* __restrict__ W,
    const float* __restrict__ bias, float* __restrict__ C, int m0)
{
    float (*As)[128] = (float(*)[128])smg;
    float (*Bs)[128] = (float(*)[128])(smg + 4096);

    const int tid  = threadIdx.x;
    const bool act = (tid < 256);
    const int lrow = (tid & 255) >> 1;
    const int lk4  = (tid & 1) * 4;
    const int tx = tid & 15;
    const int ty = (tid & 255) >> 4;

    ull acc2[8][4];
#pragma unroll
    for (int i = 0; i < 8; i++)
#pragma unroll
        for (int j = 0; j < 4; j++) acc2[i][j] = 0ull;

    const float* Arow = A + (size_t)(m0 + lrow) * FCN + lk4;
    const float* Wrow = W + (size_t)lrow * FCN + lk4;
    const bool   wok  = act && (lrow < NOUTC);

    for (int k0 = 0; k0 < FCN; k0 += 8) {
        float4 av = make_float4(0.f, 0.f, 0.f, 0.f);
        float4 wv = make_float4(0.f, 0.f, 0.f, 0.f);
        if (act) av = *(const float4*)(Arow + k0);
        if (wok) wv = *(const float4*)(Wrow + k0);

        __syncthreads();
        if (act) {
            As[lk4 + 0][lrow] = av.x; As[lk4 + 1][lrow] = av.y;
            As[lk4 + 2][lrow] = av.z; As[lk4 + 3][lrow] = av.w;
            Bs[lk4 + 0][lrow] = wv.x; Bs[lk4 + 1][lrow] = wv.y;
            Bs[lk4 + 2][lrow] = wv.z; Bs[lk4 + 3][lrow] = wv.w;
        }
        __syncthreads();

        if (act) {
#pragma unroll
            for (int kk = 0; kk < 8; kk++) {
                float a[8];
                *(float4*)(a)     = *(const float4*)&As[kk][ty * 4];
                *(float4*)(a + 4) = *(const float4*)&As[kk][64 + ty * 4];
                ulonglong2 b01 = *(const ulonglong2*)&Bs[kk][tx * 4];
                ulonglong2 b23 = *(const ulonglong2*)&Bs[kk][64 + tx * 4];
                ull bb[4] = { b01.x, b01.y, b23.x, b23.y };
                ull aa[8];
#pragma unroll
                for (int i = 0; i < 8; i++) aa[i] = pack2(a[i], a[i]);
#pragma unroll
                for (int i = 0; i < 8; i++)
#pragma unroll
                    for (int j = 0; j < 4; j++)
                        fma2(acc2[i][j], aa[i], bb[j]);
            }
        }
    }

    if (act) {
#pragma unroll
        for (int i = 0; i < 8; i++) {
            const int m = m0 + ((i < 4) ? (ty * 4 + i) : (64 + ty * 4 + i - 4));
            float* crow = C + (size_t)m * NOUTC;
#pragma unroll
            for (int j = 0; j < 4; j++) {
                const int nf = (j < 2) ? (tx * 4 + j * 2) : (64 + tx * 4 + (j - 2) * 2);
                float2 v = unpack2(acc2[i][j]);
                float vals[2] = { v.x, v.y };
#pragma unroll
                for (int s = 0; s < 2; s++) {
                    const int n = nf + s;
                    if (n < NOUTC) crow[n] = tanhf(vals[s] + bias[n]);
                }
            }
        }
    }
}

// ---------------------------------------------------------------------------
// Fused persistent kernel: blocks 0-95 = GRU recurrence (2 batch groups x 48),
// blocks 96-143 = consumers.
//   mode 0 (launch 1): xproj1 chunks 0..5 trailing layer-0 h.
//   mode 1 (launch 2): leading xproj1 chunks 6..7 (reads layer-0 h rows not
//     yet overwritten; recurrence cflag-gated at t=768/896), then fc chunks
//     trailing layer-1 h, then out_proj per chunk (cflag-synced).
// cflags: +10/replay (2 leading + 8 fc), mode-1 consumers only.
// ---------------------------------------------------------------------------
#define HPB      1552
#define OFF_AH   0
#define OFF_AL   24832                       // 16*1552
#define OFF_PRT  49664                       // floats from here: 8*772
#define SCR_HI   0                           // init-only W scratch (24*1552)
#define SCR_LO   37248
#define FUS_SMEM GSMEM                       // 110592 (covers both roles)

__global__ __launch_bounds__(512, 1) void fused_layer(
    const float* __restrict__ xp,            // [B,T,3H] (combined bias folded for r,z)
    const float* __restrict__ w_hh,          // [3H,H] fp32
    const float* __restrict__ b_hh,          // [3H] (n-gate bias used)
    u16* __restrict__ hhi, u16* __restrict__ hlo,
    const u16* __restrict__ cAh, const u16* __restrict__ cAl,
    const u16* __restrict__ cWh, const u16* __restrict__ cWl,
    const float* __restrict__ cbias, float* __restrict__ cC,
    int cN, int cACT, unsigned base_off,
    const u16* __restrict__ lWh, const u16* __restrict__ lWl,   // leading GEMM W
    const float* __restrict__ lbias, float* __restrict__ lC,    // leading bias/out
    const float* __restrict__ outw,          // out_proj weight (mode 1 only)
    const float* __restrict__ outb,          // out_proj bias   (mode 1 only)
    float* __restrict__ outp)                // d_out           (mode 1 only)
{
    extern __shared__ char smc[];
    unsigned sbase;
    asm("{ .reg .u64 t; cvta.to.shared.u64 t, %1; cvt.u32.u64 %0, t; }"
        : "=r"(sbase) : "l"(smc));
    const int tid = threadIdx.x;
    const bool mode1 = (outp != nullptr);

    // ======================= CONSUMER BLOCKS =======================
    if (blockIdx.x >= 96) {
        const int cid = blockIdx.x - 96;
        const unsigned f = ld_acq(&g_flags[0]);
        const unsigned base = (f / 2048u) * 2048u + base_off;
        const int tnt = cN / 64;
        const unsigned cb = mode1 ? ld_acq(&g_cflags[cid * 32]) : 0u;

        // ---- mode-1 leading phase: xproj1 chunks 6,7 ----
        if (mode1) {
            for (int c = 6; c < 8; c++) {
                for (int i = cid; i < 1152; i += 48) {
                    const int b  = i / 36;
                    const int nt = i % 36;
                    gemm_tile_hl(smc, sbase, cAh, cAl, lWh, lWl, lbias, lC,
                                 b * TLEN + c * 128, nt * 64, G3, 0);
                }
                __syncthreads();
                if (tid == 0)
                    st_rel(&g_cflags[cid * 32], cb + (unsigned)(c - 5));  // +1,+2
            }
        }

        const int tc_end = mode1 ? 8 : 6;     // mode 0: only chunks 0..5
        for (int tc = 0; tc < tc_end; tc++) {
            const unsigned target = base + (unsigned)((tc + 1) * 128);
            if (tid < 96) {
                while ((int)(ld_acq(&g_flags[tid * 32]) - target) < 0) { }
            }
            __syncthreads();
            for (int i = cid; i < 32 * tnt; i += 48) {
                const int b  = i / tnt;
                const int nt = i % tnt;
                gemm_tile_hl(smc, sbase, cAh, cAl, cWh, cWl, cbias, cC,
                             b * TLEN + tc * 128, nt * 64, cN, cACT);
            }

            // ---- mode-1 trailing out_proj for this chunk ----
            if (mode1) {
                __syncthreads();                     // all fc stores of this block issued
                if (tid == 0)
                    st_rel(&g_cflags[cid * 32], cb + (unsigned)(3 + tc)); // +3..+10
                const unsigned ctar = cb + (unsigned)(3 + tc);
                if (tid < 48) {
                    while ((int)(ld_acq(&g_cflags[tid * 32]) - ctar) < 0) { }
                }
                __syncthreads();                     // fc of chunk tc globally complete
                for (int b = cid; b < 32; b += 48)
                    out_tile(smc, cC, outw, outb, outp, b * TLEN + tc * 128);
                __syncthreads();                     // smem reuse barrier
            }
        }
        return;
    }

    // ======================= RECURRENCE BLOCKS =======================
    const int grp  = blockIdx.x / 48;        // batch group (16 batches)
    const int ub   = blockIdx.x % 48;
    const int u0g  = ub * 16;                // unit base
    const int bG0  = grp * 16;               // batch base
    const int warp = tid >> 5;
    const int lane = tid & 31;
    const int ks   = warp >> 1;              // k-slice 0..7 (96 wide)
    const int nh   = warp & 1;               // n-half 0..1 (24 rows)
    const unsigned flag_base = g_flags[blockIdx.x * 32];
    const unsigned cfbase    = (flag_base / 2048u) * 10u;

    // ---- W init: 2 passes through scratch; frags -> registers ----
    unsigned bh[3][6][2], bl[3][6][2];
    for (int p = 0; p < 2; p++) {
        for (int i = tid; i < 24 * 96; i += 512) {
            const int r  = i / 96;            // scratch row 0..23
            const int kc = (i % 96) * 8;
            const int rg = p * 24 + r;        // gh row 0..47 (gate*16+unit)
            const int gate = rg >> 4, ul = rg & 15;
            const float* ws = w_hh + (size_t)(gate * HD + u0g + ul) * HD + kc;
            float4 a = *(const float4*)(ws);
            float4 b = *(const float4*)(ws + 4);
            unsigned h0 = bfpk(a.y, a.x), h1 = bfpk(a.w, a.z);
            unsigned h2 = bfpk(b.y, b.x), h3 = bfpk(b.w, b.z);
            unsigned l0 = bfpk(a.y - bfhi(h0), a.x - bflo(h0));
            unsigned l1 = bfpk(a.w - bfhi(h1), a.z - bflo(h1));
            unsigned l2_ = bfpk(b.y - bfhi(h2), b.x - bflo(h2));
            unsigned l3 = bfpk(b.w - bfhi(h3), b.z - bflo(h3));
            *(uint4*)(smc + SCR_HI + r * HPB + kc * 2) = make_uint4(h0, h1, h2, h3);
            *(uint4*)(smc + SCR_LO + r * HPB + kc * 2) = make_uint4(l0, l1, l2_, l3);
        }
        __syncthreads();
        if (nh == p) {
            const int l2 = lane & 15;
#pragma unroll
            for (int nt = 0; nt < 3; nt++)
#pragma unroll
                for (int kt = 0; kt < 6; kt++) {
                    const int row = nt * 8 + (l2 & 7);
                    const int kel = ks * 96 + kt * 16 + ((l2 >> 3) & 1) * 8;
                    ldmx2(bh[nt][kt], sbase + SCR_HI + row * HPB + kel * 2);
                    ldmx2(bl[nt][kt], sbase + SCR_LO + row * HPB + kel * 2);
                }
        }
        __syncthreads();
    }

    // ---- gate decode (tid < 256) ----
    const int bg = tid >> 4;                 // local batch 0..15
    const int ug = tid & 15;                 // local unit 0..15
    float bias_n = 0.f, hprev = 0.f;
    if (tid < 256) bias_n = b_hh[2 * HD + u0g + ug];

    // ---- t = 0: gh = 0 (biases folded into xp for r,z) ----
    if (tid < 256) {
        const size_t xb = ((size_t)(bG0 + bg) * TLEN + 0) * G3 + (u0g + ug);
        const float gi_r = xp[xb];
        const float gi_z = xp[xb + HD];
        const float gi_n = xp[xb + 2 * HD];
        const float r = 1.f / (1.f + expf(-gi_r));
        const float z = 1.f / (1.f + expf(-gi_z));
        const float n = tanhf(gi_n + r * bias_n);
        hprev = (1.f - z) * n;
        const size_t hidx = ((size_t)(bG0 + bg) * TLEN + 0) * HD + (u0g + ug);
        unsigned ph = bfpk(hprev, hprev);
        float res = hprev - bflo(ph);
        unsigned pl = bfpk(res, res);
        hhi[hidx] = (u16)ph;
        hlo[hidx] = (u16)pl;
    }
    __syncthreads();
    if (tid == 0) st_rel(&g_flags[blockIdx.x * 32], flag_base + 1u);

    float* prt = (float*)(smc + OFF_PRT);

    for (int t = 1; t < TLEN; t++) {
        // --- mode 1: gate on leading xproj2 chunks 6/7 availability ---
        if (mode1 && (t == 768 || t == 896)) {
            const unsigned ct = cfbase + (unsigned)(t == 768 ? 1 : 2);
            if (tid < 48) {
                while ((int)(ld_acq(&g_cflags[tid * 32]) - ct) < 0) { }
            }
            __syncthreads();
        }

        // --- poll: 6 source blocks for this warp's k-slice ---
        const unsigned need = flag_base + (unsigned)t;
        if (lane < 6) {
            const unsigned* fp = &g_flags[(grp * 48 + ks * 6 + lane) * 32];
            while ((int)(ld_acq(fp) - need) < 0) { }
        }
        __syncwarp();

        // --- stage: warp (ks,nh) -> rows nh*8..+8, k in [96ks, 96ks+96) ---
        {
            const int row = nh * 8 + (lane >> 2);
            const int seg = lane & 3;
            const size_t sb = ((size_t)(bG0 + row) * TLEN + (t - 1)) * HD
                            + ks * 96 + seg * 24;
            const u16* sh = hhi + sb;
            const u16* sl = hlo + sb;
            char* dh = smc + OFF_AH + row * HPB + (ks * 96 + seg * 24) * 2;
            char* dl = smc + OFF_AL + row * HPB + (ks * 96 + seg * 24) * 2;
#pragma unroll
            for (int j = 0; j < 3; j++) {
                uint4 vh = __ldcg((const uint4*)(sh + j * 8));
                uint4 vl = __ldcg((const uint4*)(sl + j * 8));
                *(uint4*)(dh + j * 16) = vh;
                *(uint4*)(dl + j * 16) = vl;
            }
        }

        // gi prefetch (hidden under mma)
        float gi_r = 0.f, gi_z = 0.f, gi_n = 0.f;
        if (tid < 256) {
            const size_t xb = ((size_t)(bG0 + bg) * TLEN + t) * G3 + (u0g + ug);
            gi_r = xp[xb];
            gi_z = xp[xb + HD];
            gi_n = xp[xb + 2 * HD];
        }
        __syncthreads();

        // --- mma: m16 x (3 n-tiles) x 6 k-tiles, 3 split passes ---
        float acc[3][4];
#pragma unroll
        for (int nt = 0; nt < 3; nt++)
#pragma unroll
            for (int e = 0; e < 4; e++) acc[nt][e] = 0.f;

        const int q = lane >> 3;
        const int rq = (q & 1) * 8 + (lane & 7);
#pragma unroll
        for (int kt = 0; kt < 6; kt++) {
            const int kel = ks * 96 + kt * 16 + (q >> 1) * 8;
            unsigned ah[4], al[4];
            ldmx4(ah, sbase + OFF_AH + rq * HPB + kel * 2);
            ldmx4(al, sbase + OFF_AL + rq * HPB + kel * 2);
#pragma unroll
            for (int nt = 0; nt < 3; nt++) {
                mma16816(acc[nt], ah, bh[nt][kt]);
                mma16816(acc[nt], ah, bl[nt][kt]);
                mma16816(acc[nt], al, bh[nt][kt]);
            }
        }

        // --- dump partials: prt[ks*772 + batch*48 + rowg] ---
        {
            const int r0 = lane >> 2;
            const int c0 = (lane & 3) * 2;
            float* wp = prt + ks * 772;
#pragma unroll
            for (int nt = 0; nt < 3; nt++) {
                const int rowg = nh * 24 + nt * 8 + c0;
                *(float2*)(wp + r0 * 48 + rowg)       = make_float2(acc[nt][0], acc[nt][1]);
                *(float2*)(wp + (r0 + 8) * 48 + rowg) = make_float2(acc[nt][2], acc[nt][3]);
            }
        }
        __syncthreads();

        // --- gates (tid < 256) ---
        if (tid < 256) {
            float gh[3];
#pragma unroll
            for (int g = 0; g < 3; g++) {
                const int o = bg * 48 + g * 16 + ug;
                float s = 0.f;
#pragma unroll
                for (int k = 0; k < 8; k++) s += prt[k * 772 + o];
                gh[g] = s;
            }
            const float r = 1.f / (1.f + expf(-(gi_r + gh[0])));
            const float z = 1.f / (1.f + expf(-(gi_z + gh[1])));
            const float n = tanhf(gi_n + r * (gh[2] + bias_n));
            const float hnew = (1.f - z) * n + z * hprev;
            hprev = hnew;
            const size_t hidx = ((size_t)(bG0 + bg) * TLEN + t) * HD + (u0g + ug);
            unsigned ph = bfpk(hnew, hnew);
            float res = hnew - bflo(ph);
            unsigned pl = bfpk(res, res);
            hhi[hidx] = (u16)ph;
            hlo[hidx] = (u16)pl;
        }
        __syncthreads();

        if (tid == 0) st_rel(&g_flags[blockIdx.x * 32], flag_base + (unsigned)(t + 1));
    }
}

// ---------------------------------------------------------------------------
// Launch: 9 graph nodes.
// ---------------------------------------------------------------------------
extern "C" void kernel_launch(void* const* d_in, const int* in_sizes, int n_in,
                              void* d_out, int out_size)
{
    const float* features = (const float*)d_in[0];
    const float* w_ih0 = (const float*)d_in[2];
    const float* w_hh0 = (const float*)d_in[3];
    const float* b_ih0 = (const float*)d_in[4];
    const float* b_hh0 = (const float*)d_in[5];
    const float* w_ih1 = (const float*)d_in[6];
    const float* w_hh1 = (const float*)d_in[7];
    const float* b_ih1 = (const float*)d_in[8];
    const float* b_hh1 = (const float*)d_in[9];
    const float* fc_w  = (const float*)d_in[10];
    const float* fc_b  = (const float*)d_in[11];
    const float* out_w = (const float*)d_in[12];
    const float* out_b = (const float*)d_in[13];

    float *xproj, *xproj2, *fcb, *cb0, *cb1;
    u16 *fh, *fl, *hhi, *hlo, *w0h, *w0l, *w1h, *w1l, *fwh, *fwl;
    cudaGetSymbolAddress((void**)&xproj,  g_xproj);
    cudaGetSymbolAddress((void**)&xproj2, g_xproj2);
    cudaGetSymbolAddress((void**)&fcb,    g_fc);
    cudaGetSymbolAddress((void**)&cb0, g_cb0);
    cudaGetSymbolAddress((void**)&cb1, g_cb1);
    cudaGetSymbolAddress((void**)&fh,  g_fh);
    cudaGetSymbolAddress((void**)&fl,  g_fl);
    cudaGetSymbolAddress((void**)&hhi, g_hhi);
    cudaGetSymbolAddress((void**)&hlo, g_hlo);
    cudaGetSymbolAddress((void**)&w0h, g_w0h);
    cudaGetSymbolAddress((void**)&w0l, g_w0l);
    cudaGetSymbolAddress((void**)&w1h, g_w1h);
    cudaGetSymbolAddress((void**)&w1l, g_w1l);
    cudaGetSymbolAddress((void**)&fwh, g_fwh);
    cudaGetSymbolAddress((void**)&fwl, g_fwl);

    static bool attr_set = false;
    if (!attr_set) {
        cudaFuncSetAttribute(fused_layer,
                             cudaFuncAttributeMaxDynamicSharedMemorySize, (int)FUS_SMEM);
        cudaFuncSetAttribute(gemm_std,
                             cudaFuncAttributeMaxDynamicSharedMemorySize, (int)GSMEM);
        attr_set = true;
    }

    const int M = BSZ * TLEN;

    // Prep: planes + combined biases
    {
        int n4 = (BSZ * TLEN * DIN) / 4;
        pack_hl<<<(n4 + 255) / 256, 256>>>(features, fh, fl, n4);
        n4 = (G3 * DIN) / 4;
        pack_hl<<<(n4 + 255) / 256, 256>>>(w_ih0, w0h, w0l, n4);
        n4 = (G3 * HD) / 4;
        pack_hl<<<(n4 + 255) / 256, 256>>>(w_ih1, w1h, w1l, n4);
        n4 = (FCN * HD) / 4;
        pack_hl<<<(n4 + 255) / 256, 256>>>(fc_w, fwh, fwl, n4);
        combine_bias<<<(G3 + 255) / 256, 256>>>(b_ih0, b_hh0, cb0);
        combine_bias<<<(G3 + 255) / 256, 256>>>(b_ih1, b_hh1, cb1);
    }

    // xproj0 (sequential; first recurrence input)
    gemm_std<<<dim3(G3 / 64, M / 128), 256, GSMEM>>>(
        fh, fl, w0h, w0l, cb0, xproj, G3);

    // Launch 1: layer-0 recurrence + xproj1 consumers (chunks 0..5 trailing)
    fused_layer<<<144, 512, FUS_SMEM>>>(
        xproj, w_hh0, b_hh0, hhi, hlo,
        hhi, hlo, w1h, w1l, cb1, xproj2, G3, 0, 0u,
        nullptr, nullptr, nullptr, nullptr,
        nullptr, nullptr, nullptr);

    // Launch 2: layer-1 recurrence + consumers (leading xproj1 chunks 6..7,
    // fc trailing, out_proj trailing)
    fused_layer<<<144, 512, FUS_SMEM>>>(
        xproj2, w_hh1, b_hh1, hhi, hlo,
        hhi, hlo, fwh, fwl, fc_b, fcb, FCN, 1, 1024u,
        w1h, w1l, cb1, xproj2,
        out_w, out_b, (float*)d_out);
}